// round 1
// baseline (speedup 1.0000x reference)
#include <cuda_runtime.h>
#include <math.h>

// Problem constants
#define BSZ   2
#define TSZ   2048
#define CSZ   1024
#define NH    16
#define HSD   64
#define NC3   3072   // 3*C

// Scratch for qkv = x @ W + b   [B, T, 3C]  (~50 MB, static device global: allowed)
__device__ float g_qkv[(size_t)BSZ * TSZ * NC3];

// ---------------------------------------------------------------------------
// Kernel 1: QKV projection GEMM.  A[4096,1024] row-major  x  W[1024,3072]
// row-major -> g_qkv[4096,3072], + bias.  Classic 128x128x8 tiling, 8x8
// register micro-tiles, 256 threads.
// ---------------------------------------------------------------------------
__global__ __launch_bounds__(256) void qkv_gemm_kernel(
    const float* __restrict__ A,
    const float* __restrict__ W,
    const float* __restrict__ bias) {
  const int N = NC3, K = CSZ;
  __shared__ float As[8][128];   // transposed A tile
  __shared__ float Bs[8][128];

  const int tid  = threadIdx.x;
  const int aRow = tid >> 1;            // 0..127
  const int aCol = (tid & 1) << 2;      // 0 or 4
  const int bRow = tid >> 5;            // 0..7
  const int bCol = (tid & 31) << 2;     // 0..124
  const int tx   = tid & 15;            // col group
  const int ty   = tid >> 4;            // row group

  const float* Ap = A + ((size_t)(blockIdx.y * 128 + aRow)) * K + aCol;
  const float* Bp = W + (size_t)bRow * N + blockIdx.x * 128 + bCol;

  float acc[8][8] = {};

  for (int k0 = 0; k0 < K; k0 += 8) {
    float4 av = *(const float4*)(Ap + k0);
    As[aCol + 0][aRow] = av.x;
    As[aCol + 1][aRow] = av.y;
    As[aCol + 2][aRow] = av.z;
    As[aCol + 3][aRow] = av.w;
    *(float4*)&Bs[bRow][bCol] = *(const float4*)(Bp + (size_t)k0 * N);
    __syncthreads();

#pragma unroll
    for (int kk = 0; kk < 8; kk++) {
      float a[8], b[8];
#pragma unroll
      for (int i = 0; i < 8; i++) a[i] = As[kk][ty * 8 + i];
#pragma unroll
      for (int j = 0; j < 8; j++) b[j] = Bs[kk][tx * 8 + j];
#pragma unroll
      for (int i = 0; i < 8; i++)
#pragma unroll
        for (int j = 0; j < 8; j++)
          acc[i][j] = fmaf(a[i], b[j], acc[i][j]);
    }
    __syncthreads();
  }

  const int row0 = blockIdx.y * 128 + ty * 8;
  const int col0 = blockIdx.x * 128 + tx * 8;
#pragma unroll
  for (int i = 0; i < 8; i++) {
#pragma unroll
    for (int j = 0; j < 8; j++) {
      g_qkv[(size_t)(row0 + i) * N + col0 + j] = acc[i][j] + bias[col0 + j];
    }
  }
}

// ---------------------------------------------------------------------------
// Kernel 2: flash attention (fp32, online softmax).
// Grid: (q_tiles=32, heads=16, batch=2).  Block: 256 threads.
// Tiles: 64 q-rows x 64 k-rows x d=64.  Each thread owns a 4x4 micro-tile.
// Smem: Qs[64][65] + KVs[64][65] (K then reused for V) + S[64][65] + m/l/alpha.
// ---------------------------------------------------------------------------
#define SROW 65
#define ATT_SMEM_FLOATS (3 * 64 * SROW + 3 * 64)

__global__ __launch_bounds__(256) void flash_attn_kernel(
    float* __restrict__ out) {
  extern __shared__ float sm[];
  float* Qs   = sm;
  float* KVs  = sm + 64 * SROW;
  float* Sm   = sm + 2 * 64 * SROW;
  float* rowm = sm + 3 * 64 * SROW;
  float* rowl = rowm + 64;
  float* rowa = rowl + 64;

  const int qt = blockIdx.x;
  const int h  = blockIdx.y;
  const int b  = blockIdx.z;
  const int q0 = qt * 64;
  const int tid = threadIdx.x;
  const int tx = tid & 15;     // 0..15 (d / k-col direction)
  const int ty = tid >> 4;     // 0..15 (q-row direction)
  const float* qkv = g_qkv;

  // Load Q tile (pre-scaled by 1/sqrt(HS))
  for (int idx = tid; idx < 64 * 64; idx += 256) {
    int r = idx >> 6, c = idx & 63;
    Qs[r * SROW + c] =
        qkv[((size_t)(b * TSZ + q0 + r)) * NC3 + h * HSD + c] * 0.125f;
  }
  if (tid < 64) { rowm[tid] = -INFINITY; rowl[tid] = 0.f; }

  float o[4][4] = {};
  __syncthreads();

  for (int kt = 0; kt <= qt; kt++) {
    const int k0 = kt * 64;

    // Load K tile
    for (int idx = tid; idx < 64 * 64; idx += 256) {
      int r = idx >> 6, c = idx & 63;
      KVs[r * SROW + c] =
          qkv[((size_t)(b * TSZ + k0 + r)) * NC3 + CSZ + h * HSD + c];
    }
    __syncthreads();

    // S = Q K^T  (4x4 micro-tile per thread)
    float s[4][4] = {};
#pragma unroll 8
    for (int c = 0; c < 64; c++) {
      float a[4], bk[4];
#pragma unroll
      for (int ii = 0; ii < 4; ii++) a[ii]  = Qs[(ty * 4 + ii) * SROW + c];
#pragma unroll
      for (int jj = 0; jj < 4; jj++) bk[jj] = KVs[(tx * 4 + jj) * SROW + c];
#pragma unroll
      for (int ii = 0; ii < 4; ii++)
#pragma unroll
        for (int jj = 0; jj < 4; jj++)
          s[ii][jj] = fmaf(a[ii], bk[jj], s[ii][jj]);
    }

    const bool diag = (kt == qt);
#pragma unroll
    for (int ii = 0; ii < 4; ii++) {
#pragma unroll
      for (int jj = 0; jj < 4; jj++) {
        if (diag && (k0 + tx * 4 + jj) > (q0 + ty * 4 + ii))
          s[ii][jj] = -INFINITY;
        Sm[(ty * 4 + ii) * SROW + tx * 4 + jj] = s[ii][jj];
      }
    }
    __syncthreads();

    // Load V tile (overwrites K — safe after the sync above),
    // while threads 0..63 also do the per-row online-softmax update.
    for (int idx = tid; idx < 64 * 64; idx += 256) {
      int r = idx >> 6, c = idx & 63;
      KVs[r * SROW + c] =
          qkv[((size_t)(b * TSZ + k0 + r)) * NC3 + 2 * CSZ + h * HSD + c];
    }
    if (tid < 64) {
      const int i = tid;
      float mold = rowm[i];
      float mx = mold;
#pragma unroll 8
      for (int j = 0; j < 64; j++) mx = fmaxf(mx, Sm[i * SROW + j]);
      float alpha = expf(mold - mx);   // expf(-inf)=0 on first tile
      float sum = 0.f;
#pragma unroll 8
      for (int j = 0; j < 64; j++) {
        float p = expf(Sm[i * SROW + j] - mx);
        Sm[i * SROW + j] = p;
        sum += p;
      }
      rowm[i] = mx;
      rowl[i] = rowl[i] * alpha + sum;
      rowa[i] = alpha;
    }
    __syncthreads();

    // O = O * alpha + P @ V
#pragma unroll
    for (int ii = 0; ii < 4; ii++) {
      float al = rowa[ty * 4 + ii];
#pragma unroll
      for (int jj = 0; jj < 4; jj++) o[ii][jj] *= al;
    }
#pragma unroll 8
    for (int j = 0; j < 64; j++) {
      float p[4], v[4];
#pragma unroll
      for (int ii = 0; ii < 4; ii++) p[ii] = Sm[(ty * 4 + ii) * SROW + j];
#pragma unroll
      for (int jj = 0; jj < 4; jj++) v[jj] = KVs[j * SROW + tx * 4 + jj];
#pragma unroll
      for (int ii = 0; ii < 4; ii++)
#pragma unroll
        for (int jj = 0; jj < 4; jj++)
          o[ii][jj] = fmaf(p[ii], v[jj], o[ii][jj]);
    }
    __syncthreads();
  }

  // Normalize and write out[b, q, h*64 + d]
#pragma unroll
  for (int ii = 0; ii < 4; ii++) {
    float inv = 1.f / rowl[ty * 4 + ii];
#pragma unroll
    for (int jj = 0; jj < 4; jj++) {
      out[((size_t)(b * TSZ + q0 + ty * 4 + ii)) * CSZ + h * HSD + tx * 4 + jj] =
          o[ii][jj] * inv;
    }
  }
}

// ---------------------------------------------------------------------------
extern "C" void kernel_launch(void* const* d_in, const int* in_sizes, int n_in,
                              void* d_out, int out_size) {
  const float* x    = (const float*)d_in[0];
  const float* W    = (const float*)d_in[1];
  const float* bias = (const float*)d_in[2];
  float* out = (float*)d_out;

  (void)in_sizes; (void)n_in; (void)out_size;

  dim3 g1(NC3 / 128, (BSZ * TSZ) / 128);   // (24, 32)
  qkv_gemm_kernel<<<g1, 256>>>(x, W, bias);

  const int smem_bytes = ATT_SMEM_FLOATS * sizeof(float);   // 50688
  cudaFuncSetAttribute(flash_attn_kernel,
                       cudaFuncAttributeMaxDynamicSharedMemorySize, smem_bytes);
  dim3 g2(TSZ / 64, NH, BSZ);              // (32, 16, 2)
  flash_attn_kernel<<<g2, 256, smem_bytes>>>(out);
}

// round 2
// speedup vs baseline: 1.0922x; 1.0922x over previous
#include <cuda_runtime.h>
#include <math.h>

// Problem constants
#define BSZ   2
#define TSZ   2048
#define CSZ   1024
#define NH    16
#define HSD   64
#define NC3   3072   // 3*C

// Scratch for qkv = x @ W + b   [B, T, 3C]
__device__ float g_qkv[(size_t)BSZ * TSZ * NC3];

// ---------------------------------------------------------------------------
// Kernel 1: QKV projection GEMM (unchanged — runs at ~fp32 FFMA peak).
// ---------------------------------------------------------------------------
__global__ __launch_bounds__(256) void qkv_gemm_kernel(
    const float* __restrict__ A,
    const float* __restrict__ W,
    const float* __restrict__ bias) {
  const int N = NC3, K = CSZ;
  __shared__ float As[8][128];
  __shared__ float Bs[8][128];

  const int tid  = threadIdx.x;
  const int aRow = tid >> 1;
  const int aCol = (tid & 1) << 2;
  const int bRow = tid >> 5;
  const int bCol = (tid & 31) << 2;
  const int tx   = tid & 15;
  const int ty   = tid >> 4;

  const float* Ap = A + ((size_t)(blockIdx.y * 128 + aRow)) * K + aCol;
  const float* Bp = W + (size_t)bRow * N + blockIdx.x * 128 + bCol;

  float acc[8][8] = {};

  for (int k0 = 0; k0 < K; k0 += 8) {
    float4 av = *(const float4*)(Ap + k0);
    As[aCol + 0][aRow] = av.x;
    As[aCol + 1][aRow] = av.y;
    As[aCol + 2][aRow] = av.z;
    As[aCol + 3][aRow] = av.w;
    *(float4*)&Bs[bRow][bCol] = *(const float4*)(Bp + (size_t)k0 * N);
    __syncthreads();

#pragma unroll
    for (int kk = 0; kk < 8; kk++) {
      float a[8], b[8];
#pragma unroll
      for (int i = 0; i < 8; i++) a[i] = As[kk][ty * 8 + i];
#pragma unroll
      for (int j = 0; j < 8; j++) b[j] = Bs[kk][tx * 8 + j];
#pragma unroll
      for (int i = 0; i < 8; i++)
#pragma unroll
        for (int j = 0; j < 8; j++)
          acc[i][j] = fmaf(a[i], b[j], acc[i][j]);
    }
    __syncthreads();
  }

  const int row0 = blockIdx.y * 128 + ty * 8;
  const int col0 = blockIdx.x * 128 + tx * 8;
#pragma unroll
  for (int i = 0; i < 8; i++) {
#pragma unroll
    for (int j = 0; j < 8; j++) {
      g_qkv[(size_t)(row0 + i) * N + col0 + j] = acc[i][j] + bias[col0 + j];
    }
  }
}

// ---------------------------------------------------------------------------
// Kernel 2: flash attention, fp32, Tq=128 x Tk=64 tiles, 8x4 register
// micro-tile per thread (256 threads), all smem operand reads as LDS.128.
//
// Smem layout (floats):
//   Qt[64][132]   Q transposed [d][row]   (8448)
//   Kt[64][68]    K transposed [d][kcol]  (4352)
//   Vt[64][68]    V row-major  [k][d]     (4352)
//   St[64][132]   S transposed [kcol][row](8448)
//   rowm/rowl/rowa[128]                   (384)
// total = 25984 floats = 103,936 B  -> 2 CTAs/SM
// ---------------------------------------------------------------------------
#define TQ 128
#define TK 64
#define QST 132   // row stride for Qt/St (16B aligned, padded)
#define KST 68    // row stride for Kt/Vt

#define OFF_QT 0
#define OFF_KT (64 * QST)
#define OFF_VT (OFF_KT + 64 * KST)
#define OFF_ST (OFF_VT + 64 * KST)
#define OFF_RM (OFF_ST + 64 * QST)
#define ATT_SMEM_FLOATS (OFF_RM + 3 * TQ)

__global__ __launch_bounds__(256, 2) void flash_attn_kernel(
    float* __restrict__ out) {
  extern __shared__ float sm[];
  float* Qt   = sm + OFF_QT;
  float* Kt   = sm + OFF_KT;
  float* Vt   = sm + OFF_VT;
  float* St   = sm + OFF_ST;
  float* rowm = sm + OFF_RM;
  float* rowl = rowm + TQ;
  float* rowa = rowl + TQ;

  // heavy q-tiles first for wave balance
  const int qt = gridDim.x - 1 - blockIdx.x;
  const int h  = blockIdx.y;
  const int b  = blockIdx.z;
  const int q0 = qt * TQ;
  const int tid = threadIdx.x;
  const int tx = tid & 15;          // 0..15 -> 4 k-cols / d-cols
  const int ty = tid >> 4;          // 0..15 -> 8 q-rows
  const float* qkv = g_qkv;

  // ---- Load Q tile transposed, pre-scaled by 1/sqrt(HS) ----
  // 128 rows x 64 d  -> Qt[d][row]
  for (int idx = tid; idx < TQ * 16; idx += 256) {
    int r  = idx >> 4;
    int c4 = (idx & 15) << 2;
    float4 v = *(const float4*)&qkv[((size_t)(b * TSZ + q0 + r)) * NC3 +
                                    h * HSD + c4];
    Qt[(c4 + 0) * QST + r] = v.x * 0.125f;
    Qt[(c4 + 1) * QST + r] = v.y * 0.125f;
    Qt[(c4 + 2) * QST + r] = v.z * 0.125f;
    Qt[(c4 + 3) * QST + r] = v.w * 0.125f;
  }
  if (tid < TQ) { rowm[tid] = -INFINITY; rowl[tid] = 0.f; }

  float o[8][4] = {};
  __syncthreads();

  const int last_kt = (q0 + TQ - 1) / TK;   // = 2*qt + 1
  for (int kt = 0; kt <= last_kt; kt++) {
    const int k0 = kt * TK;

    // ---- Load K (transposed) and V (row-major) tiles ----
    for (int idx = tid; idx < TK * 16; idx += 256) {
      int r  = idx >> 4;
      int c4 = (idx & 15) << 2;
      const size_t base = ((size_t)(b * TSZ + k0 + r)) * NC3 + h * HSD;
      float4 kv = *(const float4*)&qkv[base + CSZ + c4];
      Kt[(c4 + 0) * KST + r] = kv.x;
      Kt[(c4 + 1) * KST + r] = kv.y;
      Kt[(c4 + 2) * KST + r] = kv.z;
      Kt[(c4 + 3) * KST + r] = kv.w;
      float4 vv = *(const float4*)&qkv[base + 2 * CSZ + c4];
      *(float4*)&Vt[r * KST + c4] = vv;
    }
    __syncthreads();

    // ---- S = Q K^T : 8x4 micro-tile ----
    float s[8][4] = {};
#pragma unroll 8
    for (int c = 0; c < 64; c++) {
      float4 a0 = *(const float4*)&Qt[c * QST + ty * 8];
      float4 a1 = *(const float4*)&Qt[c * QST + ty * 8 + 4];
      float4 bk = *(const float4*)&Kt[c * KST + tx * 4];
      const float a[8] = {a0.x, a0.y, a0.z, a0.w, a1.x, a1.y, a1.z, a1.w};
      const float bb[4] = {bk.x, bk.y, bk.z, bk.w};
#pragma unroll
      for (int ii = 0; ii < 8; ii++)
#pragma unroll
        for (int jj = 0; jj < 4; jj++)
          s[ii][jj] = fmaf(a[ii], bb[jj], s[ii][jj]);
    }

    // ---- causal mask (only needed on diagonal-ish tiles) + store S^T ----
    const bool need_mask = (k0 + TK - 1) > q0;
    if (need_mask) {
#pragma unroll
      for (int ii = 0; ii < 8; ii++)
#pragma unroll
        for (int jj = 0; jj < 4; jj++)
          if ((k0 + tx * 4 + jj) > (q0 + ty * 8 + ii))
            s[ii][jj] = -INFINITY;
    }
#pragma unroll
    for (int jj = 0; jj < 4; jj++) {
      float4 w0 = make_float4(s[0][jj], s[1][jj], s[2][jj], s[3][jj]);
      float4 w1 = make_float4(s[4][jj], s[5][jj], s[6][jj], s[7][jj]);
      *(float4*)&St[(tx * 4 + jj) * QST + ty * 8]     = w0;
      *(float4*)&St[(tx * 4 + jj) * QST + ty * 8 + 4] = w1;
    }
    __syncthreads();

    // ---- online softmax: 2 threads per row, 32 cols each ----
    {
      const int row  = tid >> 1;
      const int half = tid & 1;
      const int cbase = half * 32;
      float vmax = -INFINITY;
#pragma unroll 8
      for (int u = 0; u < 32; u++)
        vmax = fmaxf(vmax, St[(cbase + u) * QST + row]);
      vmax = fmaxf(vmax, __shfl_xor_sync(0xffffffffu, vmax, 1));
      const float mold = rowm[row];
      const float mx = fmaxf(mold, vmax);
      float sum = 0.f;
#pragma unroll 8
      for (int u = 0; u < 32; u++) {
        float p = __expf(St[(cbase + u) * QST + row] - mx);
        St[(cbase + u) * QST + row] = p;
        sum += p;
      }
      sum += __shfl_xor_sync(0xffffffffu, sum, 1);
      if (half == 0) {
        float alpha = __expf(mold - mx);   // 0 on first tile
        rowm[row] = mx;
        rowl[row] = rowl[row] * alpha + sum;
        rowa[row] = alpha;
      }
    }
    __syncthreads();

    // ---- O = O*alpha + P @ V ----
#pragma unroll
    for (int ii = 0; ii < 8; ii++) {
      float al = rowa[ty * 8 + ii];
#pragma unroll
      for (int jj = 0; jj < 4; jj++) o[ii][jj] *= al;
    }
#pragma unroll 8
    for (int j = 0; j < 64; j++) {
      float4 p0 = *(const float4*)&St[j * QST + ty * 8];
      float4 p1 = *(const float4*)&St[j * QST + ty * 8 + 4];
      float4 vv = *(const float4*)&Vt[j * KST + tx * 4];
      const float p[8] = {p0.x, p0.y, p0.z, p0.w, p1.x, p1.y, p1.z, p1.w};
      const float v[4] = {vv.x, vv.y, vv.z, vv.w};
#pragma unroll
      for (int ii = 0; ii < 8; ii++)
#pragma unroll
        for (int jj = 0; jj < 4; jj++)
          o[ii][jj] = fmaf(p[ii], v[jj], o[ii][jj]);
    }
    __syncthreads();   // protect Kt/Vt/St for next iteration
  }

  // ---- normalize & write out[b, q, h*64 + d] ----
#pragma unroll
  for (int ii = 0; ii < 8; ii++) {
    const int r = ty * 8 + ii;
    float inv = 1.f / rowl[r];
    float4 w = make_float4(o[ii][0] * inv, o[ii][1] * inv,
                           o[ii][2] * inv, o[ii][3] * inv);
    *(float4*)&out[((size_t)(b * TSZ + q0 + r)) * CSZ + h * HSD + tx * 4] = w;
  }
}

// ---------------------------------------------------------------------------
extern "C" void kernel_launch(void* const* d_in, const int* in_sizes, int n_in,
                              void* d_out, int out_size) {
  const float* x    = (const float*)d_in[0];
  const float* W    = (const float*)d_in[1];
  const float* bias = (const float*)d_in[2];
  float* out = (float*)d_out;

  (void)in_sizes; (void)n_in; (void)out_size;

  dim3 g1(NC3 / 128, (BSZ * TSZ) / 128);   // (24, 32)
  qkv_gemm_kernel<<<g1, 256>>>(x, W, bias);

  const int smem_bytes = ATT_SMEM_FLOATS * sizeof(float);   // ~104 KB
  cudaFuncSetAttribute(flash_attn_kernel,
                       cudaFuncAttributeMaxDynamicSharedMemorySize, smem_bytes);
  dim3 g2(TSZ / TQ, NH, BSZ);              // (16, 16, 2)
  flash_attn_kernel<<<g2, 256, smem_bytes>>>(out);
}

// round 4
// speedup vs baseline: 1.4773x; 1.3526x over previous
#include <cuda_runtime.h>
#include <math.h>
#include <stdint.h>

// Problem constants
#define BSZ   2
#define TSZ   2048
#define CSZ   1024
#define NH    16
#define HSD   64
#define NC3   3072   // 3*C

// Scratch for qkv = x @ W + b   [B, T, 3C]
__device__ float g_qkv[(size_t)BSZ * TSZ * NC3];

// ===========================================================================
// helpers
// ===========================================================================
__device__ __forceinline__ uint32_t f2tf32(float f) {
  uint32_t r;
  asm("cvt.rna.tf32.f32 %0, %1;" : "=r"(r) : "f"(f));
  return r;
}
// fragment-slot swizzle: permutes the 16B/8B slot within each quad so that
// writer STS (64B-strided across lanes) hits distinct banks.
__device__ __forceinline__ int uswz(int lane) {
  int q = lane >> 2;
  return (q << 2) | ((lane + q + (q >> 2)) & 3);
}
#define MMA_TF32(d, a, b)                                                  \
  asm volatile(                                                            \
      "mma.sync.aligned.m16n8k8.row.col.f32.tf32.tf32.f32 "                \
      "{%0,%1,%2,%3}, {%4,%5,%6,%7}, {%8,%9}, {%0,%1,%2,%3};"              \
      : "+f"((d)[0]), "+f"((d)[1]), "+f"((d)[2]), "+f"((d)[3])             \
      : "r"((a).x), "r"((a).y), "r"((a).z), "r"((a).w),                    \
        "r"((b).x), "r"((b).y))

// ===========================================================================
// Kernel 1: QKV projection GEMM via mma.sync tf32 (tensor cores, base-target
// compatible).  CTA tile 128x128, K-chunk 32, double-buffered fragment-major
// SMEM.  Grid (24, 32), 256 threads, 8 warps (2m x 4n).
//
// SMEM (64KB): Afrag[2][32 groups][32 lanes] uint4   (2 x 16KB)
//              Bfrag[2][64 groups][32 lanes] uint2   (2 x 16KB)
// group = tile*4 + kstep;  lane slot swizzled by uswz().
// ===========================================================================
#define GA_BYTES 16384
#define GB_BASE  32768
#define GB_BYTES 16384
#define GSMEM_TOTAL 65536
#define NCHUNK 32

__global__ __launch_bounds__(256, 2) void qkv_gemm_mma_kernel(
    const float* __restrict__ A,
    const float* __restrict__ W,
    const float* __restrict__ bias) {
  extern __shared__ char smem[];
  const int tid  = threadIdx.x;
  const int lane = tid & 31;
  const int warp = tid >> 5;
  const int wm = warp >> 2;          // 0..1
  const int wn = warp & 3;           // 0..3
  const int m0 = blockIdx.y * 128;
  const int n0 = blockIdx.x * 128;

  // ---- writer-side A unit: (tile, kstep, row-quad) ----
  const int a_tile = tid >> 5;            // 0..7
  const int a_ks   = (tid >> 3) & 3;      // 0..3
  const int a_q    = tid & 7;             // 0..7
  const int a_perm = (a_q + (a_q >> 2)) & 3;
  const float* aP0 =
      A + (size_t)(m0 + a_tile * 16 + a_q) * CSZ + a_ks * 8;
  const int aG = (a_tile * 4 + a_ks) * 512;   // group byte offset

  // ---- writer-side B units: tid and tid+256 ----
  int b_nh[2], b_kk[2], b_ks[2], b_nt[2];
  const float* bP0[2];
  int bG[2];
#pragma unroll
  for (int i = 0; i < 2; i++) {
    int u = tid + i * 256;
    b_nh[i] = u & 1;
    b_kk[i] = (u >> 1) & 3;
    b_ks[i] = (u >> 3) & 3;
    b_nt[i] = u >> 5;                 // 0..15
    bP0[i] = W + (size_t)(b_ks[i] * 8 + b_kk[i]) * NC3 + n0 +
             b_nt[i] * 8 + b_nh[i] * 4;
    bG[i] = (b_nt[i] * 4 + b_ks[i]) * 256;
  }

  // reader lane slot offsets
  const int rl16 = uswz(lane) * 16;
  const int rl8  = uswz(lane) * 8;

  float acc[4][4][4] = {};
  float4 ar[4], br[4];

  // ---- prologue: load + store chunk 0 ----
  {
    ar[0] = *(const float4*)(aP0);
    ar[1] = *(const float4*)(aP0 + 8 * CSZ);
    ar[2] = *(const float4*)(aP0 + 4);
    ar[3] = *(const float4*)(aP0 + 8 * CSZ + 4);
#pragma unroll
    for (int i = 0; i < 2; i++) {
      br[2 * i]     = *(const float4*)(bP0[i]);
      br[2 * i + 1] = *(const float4*)(bP0[i] + 4 * NC3);
    }
    char* ab = smem;
    char* bb = smem + GB_BASE;
    const float* arf = (const float*)ar;
#pragma unroll
    for (int j = 0; j < 4; j++) {
      uint4 v;
      v.x = f2tf32(arf[0 * 4 + j]);
      v.y = f2tf32(arf[1 * 4 + j]);
      v.z = f2tf32(arf[2 * 4 + j]);
      v.w = f2tf32(arf[3 * 4 + j]);
      *(uint4*)(ab + aG + (4 * a_q + ((j + a_perm) & 3)) * 16) = v;
    }
    const float* brf = (const float*)br;
#pragma unroll
    for (int i = 0; i < 2; i++) {
#pragma unroll
      for (int j = 0; j < 4; j++) {
        int q = b_nh[i] * 4 + j;
        int slot = 4 * q + ((b_kk[i] + q + (q >> 2)) & 3);
        uint2 v;
        v.x = f2tf32(brf[(2 * i) * 4 + j]);
        v.y = f2tf32(brf[(2 * i + 1) * 4 + j]);
        *(uint2*)(bb + bG[i] + slot * 8) = v;
      }
    }
  }
  __syncthreads();

  // ---- main loop ----
  for (int c = 0; c < NCHUNK; c++) {
    const char* ab = smem + (c & 1) * GA_BYTES;
    const char* bb = smem + GB_BASE + (c & 1) * GB_BYTES;

    if (c + 1 < NCHUNK) {
      const int ko = (c + 1) * 32;
      ar[0] = *(const float4*)(aP0 + ko);
      ar[1] = *(const float4*)(aP0 + 8 * CSZ + ko);
      ar[2] = *(const float4*)(aP0 + ko + 4);
      ar[3] = *(const float4*)(aP0 + 8 * CSZ + ko + 4);
#pragma unroll
      for (int i = 0; i < 2; i++) {
        br[2 * i]     = *(const float4*)(bP0[i] + (size_t)ko * NC3);
        br[2 * i + 1] = *(const float4*)(bP0[i] + (size_t)(ko + 4) * NC3);
      }
    }

    // compute chunk c
#pragma unroll
    for (int ks = 0; ks < 4; ks++) {
      uint4 af[4];
      uint2 bf[4];
#pragma unroll
      for (int mi = 0; mi < 4; mi++)
        af[mi] = *(const uint4*)(ab + ((wm * 4 + mi) * 4 + ks) * 512 + rl16);
#pragma unroll
      for (int ni = 0; ni < 4; ni++)
        bf[ni] = *(const uint2*)(bb + ((wn * 4 + ni) * 4 + ks) * 256 + rl8);
#pragma unroll
      for (int mi = 0; mi < 4; mi++)
#pragma unroll
        for (int ni = 0; ni < 4; ni++)
          MMA_TF32(acc[mi][ni], af[mi], bf[ni]);
    }

    if (c + 1 < NCHUNK) {
      char* nab = smem + ((c + 1) & 1) * GA_BYTES;
      char* nbb = smem + GB_BASE + ((c + 1) & 1) * GB_BYTES;
      const float* arf = (const float*)ar;
#pragma unroll
      for (int j = 0; j < 4; j++) {
        uint4 v;
        v.x = f2tf32(arf[0 * 4 + j]);
        v.y = f2tf32(arf[1 * 4 + j]);
        v.z = f2tf32(arf[2 * 4 + j]);
        v.w = f2tf32(arf[3 * 4 + j]);
        *(uint4*)(nab + aG + (4 * a_q + ((j + a_perm) & 3)) * 16) = v;
      }
      const float* brf = (const float*)br;
#pragma unroll
      for (int i = 0; i < 2; i++) {
#pragma unroll
        for (int j = 0; j < 4; j++) {
          int q = b_nh[i] * 4 + j;
          int slot = 4 * q + ((b_kk[i] + q + (q >> 2)) & 3);
          uint2 v;
          v.x = f2tf32(brf[(2 * i) * 4 + j]);
          v.y = f2tf32(brf[(2 * i + 1) * 4 + j]);
          *(uint2*)(nbb + bG[i] + slot * 8) = v;
        }
      }
    }
    __syncthreads();
  }

  // ---- epilogue: acc + bias -> g_qkv ----
  const int r_base = m0 + wm * 64 + (lane >> 2);
  const int c_base = n0 + wn * 32 + 2 * (lane & 3);
#pragma unroll
  for (int ni = 0; ni < 4; ni++) {
    const int gc = c_base + ni * 8;
    float2 bv = *(const float2*)&bias[gc];
#pragma unroll
    for (int mi = 0; mi < 4; mi++) {
      const int gr = r_base + mi * 16;
      float2 o0 = make_float2(acc[mi][ni][0] + bv.x, acc[mi][ni][1] + bv.y);
      float2 o1 = make_float2(acc[mi][ni][2] + bv.x, acc[mi][ni][3] + bv.y);
      *(float2*)&g_qkv[(size_t)gr * NC3 + gc] = o0;
      *(float2*)&g_qkv[(size_t)(gr + 8) * NC3 + gc] = o1;
    }
  }
}

// ---------------------------------------------------------------------------
// Kernel 2: flash attention (unchanged R2 version — ~77% of FFMA ceiling).
// ---------------------------------------------------------------------------
#define TQ 128
#define TK 64
#define QST 132
#define KST 68

#define OFF_QT 0
#define OFF_KT (64 * QST)
#define OFF_VT (OFF_KT + 64 * KST)
#define OFF_ST (OFF_VT + 64 * KST)
#define OFF_RM (OFF_ST + 64 * QST)
#define ATT_SMEM_FLOATS (OFF_RM + 3 * TQ)

__global__ __launch_bounds__(256, 2) void flash_attn_kernel(
    float* __restrict__ out) {
  extern __shared__ float sm[];
  float* Qt   = sm + OFF_QT;
  float* Kt   = sm + OFF_KT;
  float* Vt   = sm + OFF_VT;
  float* St   = sm + OFF_ST;
  float* rowm = sm + OFF_RM;
  float* rowl = rowm + TQ;
  float* rowa = rowl + TQ;

  const int qt = gridDim.x - 1 - blockIdx.x;
  const int h  = blockIdx.y;
  const int b  = blockIdx.z;
  const int q0 = qt * TQ;
  const int tid = threadIdx.x;
  const int tx = tid & 15;
  const int ty = tid >> 4;
  const float* qkv = g_qkv;

  for (int idx = tid; idx < TQ * 16; idx += 256) {
    int r  = idx >> 4;
    int c4 = (idx & 15) << 2;
    float4 v = *(const float4*)&qkv[((size_t)(b * TSZ + q0 + r)) * NC3 +
                                    h * HSD + c4];
    Qt[(c4 + 0) * QST + r] = v.x * 0.125f;
    Qt[(c4 + 1) * QST + r] = v.y * 0.125f;
    Qt[(c4 + 2) * QST + r] = v.z * 0.125f;
    Qt[(c4 + 3) * QST + r] = v.w * 0.125f;
  }
  if (tid < TQ) { rowm[tid] = -INFINITY; rowl[tid] = 0.f; }

  float o[8][4] = {};
  __syncthreads();

  const int last_kt = (q0 + TQ - 1) / TK;
  for (int kt = 0; kt <= last_kt; kt++) {
    const int k0 = kt * TK;

    for (int idx = tid; idx < TK * 16; idx += 256) {
      int r  = idx >> 4;
      int c4 = (idx & 15) << 2;
      const size_t base = ((size_t)(b * TSZ + k0 + r)) * NC3 + h * HSD;
      float4 kv = *(const float4*)&qkv[base + CSZ + c4];
      Kt[(c4 + 0) * KST + r] = kv.x;
      Kt[(c4 + 1) * KST + r] = kv.y;
      Kt[(c4 + 2) * KST + r] = kv.z;
      Kt[(c4 + 3) * KST + r] = kv.w;
      float4 vv = *(const float4*)&qkv[base + 2 * CSZ + c4];
      *(float4*)&Vt[r * KST + c4] = vv;
    }
    __syncthreads();

    float s[8][4] = {};
#pragma unroll 8
    for (int c = 0; c < 64; c++) {
      float4 a0 = *(const float4*)&Qt[c * QST + ty * 8];
      float4 a1 = *(const float4*)&Qt[c * QST + ty * 8 + 4];
      float4 bk = *(const float4*)&Kt[c * KST + tx * 4];
      const float a[8] = {a0.x, a0.y, a0.z, a0.w, a1.x, a1.y, a1.z, a1.w};
      const float bb[4] = {bk.x, bk.y, bk.z, bk.w};
#pragma unroll
      for (int ii = 0; ii < 8; ii++)
#pragma unroll
        for (int jj = 0; jj < 4; jj++)
          s[ii][jj] = fmaf(a[ii], bb[jj], s[ii][jj]);
    }

    const bool need_mask = (k0 + TK - 1) > q0;
    if (need_mask) {
#pragma unroll
      for (int ii = 0; ii < 8; ii++)
#pragma unroll
        for (int jj = 0; jj < 4; jj++)
          if ((k0 + tx * 4 + jj) > (q0 + ty * 8 + ii))
            s[ii][jj] = -INFINITY;
    }
#pragma unroll
    for (int jj = 0; jj < 4; jj++) {
      float4 w0 = make_float4(s[0][jj], s[1][jj], s[2][jj], s[3][jj]);
      float4 w1 = make_float4(s[4][jj], s[5][jj], s[6][jj], s[7][jj]);
      *(float4*)&St[(tx * 4 + jj) * QST + ty * 8]     = w0;
      *(float4*)&St[(tx * 4 + jj) * QST + ty * 8 + 4] = w1;
    }
    __syncthreads();

    {
      const int row  = tid >> 1;
      const int half = tid & 1;
      const int cbase = half * 32;
      float vmax = -INFINITY;
#pragma unroll 8
      for (int u = 0; u < 32; u++)
        vmax = fmaxf(vmax, St[(cbase + u) * QST + row]);
      vmax = fmaxf(vmax, __shfl_xor_sync(0xffffffffu, vmax, 1));
      const float mold = rowm[row];
      const float mx = fmaxf(mold, vmax);
      float sum = 0.f;
#pragma unroll 8
      for (int u = 0; u < 32; u++) {
        float p = __expf(St[(cbase + u) * QST + row] - mx);
        St[(cbase + u) * QST + row] = p;
        sum += p;
      }
      sum += __shfl_xor_sync(0xffffffffu, sum, 1);
      if (half == 0) {
        float alpha = __expf(mold - mx);
        rowm[row] = mx;
        rowl[row] = rowl[row] * alpha + sum;
        rowa[row] = alpha;
      }
    }
    __syncthreads();

#pragma unroll
    for (int ii = 0; ii < 8; ii++) {
      float al = rowa[ty * 8 + ii];
#pragma unroll
      for (int jj = 0; jj < 4; jj++) o[ii][jj] *= al;
    }
#pragma unroll 8
    for (int j = 0; j < 64; j++) {
      float4 p0 = *(const float4*)&St[j * QST + ty * 8];
      float4 p1 = *(const float4*)&St[j * QST + ty * 8 + 4];
      float4 vv = *(const float4*)&Vt[j * KST + tx * 4];
      const float p[8] = {p0.x, p0.y, p0.z, p0.w, p1.x, p1.y, p1.z, p1.w};
      const float v[4] = {vv.x, vv.y, vv.z, vv.w};
#pragma unroll
      for (int ii = 0; ii < 8; ii++)
#pragma unroll
        for (int jj = 0; jj < 4; jj++)
          o[ii][jj] = fmaf(p[ii], v[jj], o[ii][jj]);
    }
    __syncthreads();
  }

#pragma unroll
  for (int ii = 0; ii < 8; ii++) {
    const int r = ty * 8 + ii;
    float inv = 1.f / rowl[r];
    float4 w = make_float4(o[ii][0] * inv, o[ii][1] * inv,
                           o[ii][2] * inv, o[ii][3] * inv);
    *(float4*)&out[((size_t)(b * TSZ + q0 + r)) * CSZ + h * HSD + tx * 4] = w;
  }
}

// ---------------------------------------------------------------------------
extern "C" void kernel_launch(void* const* d_in, const int* in_sizes, int n_in,
                              void* d_out, int out_size) {
  const float* x    = (const float*)d_in[0];
  const float* W    = (const float*)d_in[1];
  const float* bias = (const float*)d_in[2];
  float* out = (float*)d_out;

  (void)in_sizes; (void)n_in; (void)out_size;

  cudaFuncSetAttribute(qkv_gemm_mma_kernel,
                       cudaFuncAttributeMaxDynamicSharedMemorySize,
                       GSMEM_TOTAL);
  dim3 g1(NC3 / 128, (BSZ * TSZ) / 128);   // (24, 32)
  qkv_gemm_mma_kernel<<<g1, 256, GSMEM_TOTAL>>>(x, W, bias);

  const int smem_bytes = ATT_SMEM_FLOATS * sizeof(float);   // ~104 KB
  cudaFuncSetAttribute(flash_attn_kernel,
                       cudaFuncAttributeMaxDynamicSharedMemorySize, smem_bytes);
  dim3 g2(TSZ / TQ, NH, BSZ);              // (16, 16, 2)
  flash_attn_kernel<<<g2, 256, smem_bytes>>>(out);
}

// round 5
// speedup vs baseline: 1.5829x; 1.0715x over previous
#include <cuda_runtime.h>
#include <math.h>
#include <stdint.h>

// Problem constants
#define BSZ   2
#define TSZ   2048
#define CSZ   1024
#define NH    16
#define HSD   64
#define NC3   3072   // 3*C

// Scratch for qkv = x @ W + b   [B, T, 3C]
__device__ float g_qkv[(size_t)BSZ * TSZ * NC3];

// ===========================================================================
// helpers
// ===========================================================================
__device__ __forceinline__ uint32_t f2tf32(float f) {
  uint32_t r;
  asm("cvt.rna.tf32.f32 %0, %1;" : "=r"(r) : "f"(f));
  return r;
}
__device__ __forceinline__ int uswz(int lane) {
  int q = lane >> 2;
  return (q << 2) | ((lane + q + (q >> 2)) & 3);
}
#define MMA_TF32(d, a, b)                                                  \
  asm volatile(                                                            \
      "mma.sync.aligned.m16n8k8.row.col.f32.tf32.tf32.f32 "                \
      "{%0,%1,%2,%3}, {%4,%5,%6,%7}, {%8,%9}, {%0,%1,%2,%3};"              \
      : "+f"((d)[0]), "+f"((d)[1]), "+f"((d)[2]), "+f"((d)[3])             \
      : "r"((a).x), "r"((a).y), "r"((a).z), "r"((a).w),                    \
        "r"((b).x), "r"((b).y))

// ===========================================================================
// Kernel 1: QKV projection GEMM via mma.sync tf32 (unchanged from R4).
// ===========================================================================
#define GA_BYTES 16384
#define GB_BASE  32768
#define GB_BYTES 16384
#define GSMEM_TOTAL 65536
#define NCHUNK 32

__global__ __launch_bounds__(256, 2) void qkv_gemm_mma_kernel(
    const float* __restrict__ A,
    const float* __restrict__ W,
    const float* __restrict__ bias) {
  extern __shared__ char smem[];
  const int tid  = threadIdx.x;
  const int lane = tid & 31;
  const int warp = tid >> 5;
  const int wm = warp >> 2;
  const int wn = warp & 3;
  const int m0 = blockIdx.y * 128;
  const int n0 = blockIdx.x * 128;

  const int a_tile = tid >> 5;
  const int a_ks   = (tid >> 3) & 3;
  const int a_q    = tid & 7;
  const int a_perm = (a_q + (a_q >> 2)) & 3;
  const float* aP0 =
      A + (size_t)(m0 + a_tile * 16 + a_q) * CSZ + a_ks * 8;
  const int aG = (a_tile * 4 + a_ks) * 512;

  int b_nh[2], b_kk[2], b_ks[2], b_nt[2];
  const float* bP0[2];
  int bG[2];
#pragma unroll
  for (int i = 0; i < 2; i++) {
    int u = tid + i * 256;
    b_nh[i] = u & 1;
    b_kk[i] = (u >> 1) & 3;
    b_ks[i] = (u >> 3) & 3;
    b_nt[i] = u >> 5;
    bP0[i] = W + (size_t)(b_ks[i] * 8 + b_kk[i]) * NC3 + n0 +
             b_nt[i] * 8 + b_nh[i] * 4;
    bG[i] = (b_nt[i] * 4 + b_ks[i]) * 256;
  }

  const int rl16 = uswz(lane) * 16;
  const int rl8  = uswz(lane) * 8;

  float acc[4][4][4] = {};
  float4 ar[4], br[4];

  {
    ar[0] = *(const float4*)(aP0);
    ar[1] = *(const float4*)(aP0 + 8 * CSZ);
    ar[2] = *(const float4*)(aP0 + 4);
    ar[3] = *(const float4*)(aP0 + 8 * CSZ + 4);
#pragma unroll
    for (int i = 0; i < 2; i++) {
      br[2 * i]     = *(const float4*)(bP0[i]);
      br[2 * i + 1] = *(const float4*)(bP0[i] + 4 * NC3);
    }
    char* ab = smem;
    char* bb = smem + GB_BASE;
    const float* arf = (const float*)ar;
#pragma unroll
    for (int j = 0; j < 4; j++) {
      uint4 v;
      v.x = f2tf32(arf[0 * 4 + j]);
      v.y = f2tf32(arf[1 * 4 + j]);
      v.z = f2tf32(arf[2 * 4 + j]);
      v.w = f2tf32(arf[3 * 4 + j]);
      *(uint4*)(ab + aG + (4 * a_q + ((j + a_perm) & 3)) * 16) = v;
    }
    const float* brf = (const float*)br;
#pragma unroll
    for (int i = 0; i < 2; i++) {
#pragma unroll
      for (int j = 0; j < 4; j++) {
        int q = b_nh[i] * 4 + j;
        int slot = 4 * q + ((b_kk[i] + q + (q >> 2)) & 3);
        uint2 v;
        v.x = f2tf32(brf[(2 * i) * 4 + j]);
        v.y = f2tf32(brf[(2 * i + 1) * 4 + j]);
        *(uint2*)(bb + bG[i] + slot * 8) = v;
      }
    }
  }
  __syncthreads();

  for (int c = 0; c < NCHUNK; c++) {
    const char* ab = smem + (c & 1) * GA_BYTES;
    const char* bb = smem + GB_BASE + (c & 1) * GB_BYTES;

    if (c + 1 < NCHUNK) {
      const int ko = (c + 1) * 32;
      ar[0] = *(const float4*)(aP0 + ko);
      ar[1] = *(const float4*)(aP0 + 8 * CSZ + ko);
      ar[2] = *(const float4*)(aP0 + ko + 4);
      ar[3] = *(const float4*)(aP0 + 8 * CSZ + ko + 4);
#pragma unroll
      for (int i = 0; i < 2; i++) {
        br[2 * i]     = *(const float4*)(bP0[i] + (size_t)ko * NC3);
        br[2 * i + 1] = *(const float4*)(bP0[i] + (size_t)(ko + 4) * NC3);
      }
    }

#pragma unroll
    for (int ks = 0; ks < 4; ks++) {
      uint4 af[4];
      uint2 bf[4];
#pragma unroll
      for (int mi = 0; mi < 4; mi++)
        af[mi] = *(const uint4*)(ab + ((wm * 4 + mi) * 4 + ks) * 512 + rl16);
#pragma unroll
      for (int ni = 0; ni < 4; ni++)
        bf[ni] = *(const uint2*)(bb + ((wn * 4 + ni) * 4 + ks) * 256 + rl8);
#pragma unroll
      for (int mi = 0; mi < 4; mi++)
#pragma unroll
        for (int ni = 0; ni < 4; ni++)
          MMA_TF32(acc[mi][ni], af[mi], bf[ni]);
    }

    if (c + 1 < NCHUNK) {
      char* nab = smem + ((c + 1) & 1) * GA_BYTES;
      char* nbb = smem + GB_BASE + ((c + 1) & 1) * GB_BYTES;
      const float* arf = (const float*)ar;
#pragma unroll
      for (int j = 0; j < 4; j++) {
        uint4 v;
        v.x = f2tf32(arf[0 * 4 + j]);
        v.y = f2tf32(arf[1 * 4 + j]);
        v.z = f2tf32(arf[2 * 4 + j]);
        v.w = f2tf32(arf[3 * 4 + j]);
        *(uint4*)(nab + aG + (4 * a_q + ((j + a_perm) & 3)) * 16) = v;
      }
      const float* brf = (const float*)br;
#pragma unroll
      for (int i = 0; i < 2; i++) {
#pragma unroll
        for (int j = 0; j < 4; j++) {
          int q = b_nh[i] * 4 + j;
          int slot = 4 * q + ((b_kk[i] + q + (q >> 2)) & 3);
          uint2 v;
          v.x = f2tf32(brf[(2 * i) * 4 + j]);
          v.y = f2tf32(brf[(2 * i + 1) * 4 + j]);
          *(uint2*)(nbb + bG[i] + slot * 8) = v;
        }
      }
    }
    __syncthreads();
  }

  const int r_base = m0 + wm * 64 + (lane >> 2);
  const int c_base = n0 + wn * 32 + 2 * (lane & 3);
#pragma unroll
  for (int ni = 0; ni < 4; ni++) {
    const int gc = c_base + ni * 8;
    float2 bv = *(const float2*)&bias[gc];
#pragma unroll
    for (int mi = 0; mi < 4; mi++) {
      const int gr = r_base + mi * 16;
      float2 o0 = make_float2(acc[mi][ni][0] + bv.x, acc[mi][ni][1] + bv.y);
      float2 o1 = make_float2(acc[mi][ni][2] + bv.x, acc[mi][ni][3] + bv.y);
      *(float2*)&g_qkv[(size_t)gr * NC3 + gc] = o0;
      *(float2*)&g_qkv[(size_t)(gr + 8) * NC3 + gc] = o1;
    }
  }
}

// ===========================================================================
// Kernel 2: flash attention on mma.sync tf32.
// TQ=128 (8 warps x 16 q-rows), TK=64, D=64.  Fragment-major smem for
// Q (A-frag, 512B groups), K and V (B-frag, 256B groups).  Register
// softmax (quad shuffles), acc->A-operand transpose via 8 shuffles/ks.
// Smem: Qf 32KB @0, Kf 16KB @32K, Vf 16KB @48K = 64KB.
// ===========================================================================
#define FTQ 128
#define FTK 64
#define QF_OFF 0
#define KF_OFF (32 * 1024)
#define VF_OFF (48 * 1024)
#define FSMEM  (64 * 1024)

__global__ __launch_bounds__(256, 2) void flash_attn_mma_kernel(
    float* __restrict__ out) {
  extern __shared__ char fsm[];
  const int tid  = threadIdx.x;
  const int lane = tid & 31;
  const int warp = tid >> 5;
  const int qt = gridDim.x - 1 - blockIdx.x;   // heavy tiles first
  const int h  = blockIdx.y;
  const int b  = blockIdx.z;
  const int q0 = qt * FTQ;
  const float* qkv = g_qkv;

  // ---- build Q fragments once (A-frag layout, scaled by 1/8) ----
#pragma unroll
  for (int i = 0; i < 2; i++) {
    const int u = tid + i * 256;
    const int wt = u >> 6, ks = (u >> 3) & 7, q = u & 7;
    const float* qp =
        qkv + (size_t)(b * TSZ + q0 + wt * 16 + q) * NC3 + h * HSD + ks * 8;
    float4 r0a = *(const float4*)(qp);
    float4 r0b = *(const float4*)(qp + 4);
    float4 r1a = *(const float4*)(qp + (size_t)8 * NC3);
    float4 r1b = *(const float4*)(qp + (size_t)8 * NC3 + 4);
    const float r0[8] = {r0a.x, r0a.y, r0a.z, r0a.w, r0b.x, r0b.y, r0b.z, r0b.w};
    const float r1[8] = {r1a.x, r1a.y, r1a.z, r1a.w, r1b.x, r1b.y, r1b.z, r1b.w};
    const int perm = (q + (q >> 2)) & 3;
    char* gb = fsm + QF_OFF + (wt * 8 + ks) * 512;
#pragma unroll
    for (int j = 0; j < 4; j++) {
      uint4 v;
      v.x = f2tf32(r0[j] * 0.125f);
      v.y = f2tf32(r1[j] * 0.125f);
      v.z = f2tf32(r0[j + 4] * 0.125f);
      v.w = f2tf32(r1[j + 4] * 0.125f);
      *(uint4*)(gb + (4 * q + ((j + perm) & 3)) * 16) = v;
    }
  }

  float m0 = -1e30f, m1 = -1e30f, l0 = 0.f, l1 = 0.f;
  float o[8][4] = {};
  const int wrow0 = q0 + warp * 16;
  const int qrl16 = uswz(lane) * 16;
  const int last_kt = 2 * qt + 1;

  for (int kt = 0; kt <= last_kt; kt++) {
    const int k0 = kt * FTK;

    // ---- gmem loads for K/V fragment units (overlap prev compute) ----
    float4 ka[2], kb[2], va[2], vb[2];
#pragma unroll
    for (int i = 0; i < 2; i++) {
      const int u = tid + i * 256;
      // K unit: (tt = u>>6 token tile, ks = d-step, q = token-in-tile)
      const float* kp = qkv +
          (size_t)(b * TSZ + k0 + (u >> 6) * 8 + (u & 7)) * NC3 + CSZ +
          h * HSD + ((u >> 3) & 7) * 8;
      ka[i] = *(const float4*)(kp);
      kb[i] = *(const float4*)(kp + 4);
      // V unit: (ntd = u>>6 d tile, ks = token-step, j2 = token-in-step)
      const float* vp = qkv +
          (size_t)(b * TSZ + k0 + ((u >> 3) & 7) * 8 + (u & 7)) * NC3 +
          2 * CSZ + h * HSD + (u >> 6) * 8;
      va[i] = *(const float4*)(vp);
      vb[i] = *(const float4*)(vp + 4);
    }
    __syncthreads();   // previous iteration's compute done

    // ---- store K frags (uint2 {d, d+4} per lane) ----
#pragma unroll
    for (int i = 0; i < 2; i++) {
      const int u = tid + i * 256;
      const int g = u >> 3, q = u & 7;
      char* p = fsm + KF_OFF + g * 256 + ((q ^ (g & 7)) * 32);
      uint4 w0, w1;
      w0.x = f2tf32(ka[i].x); w0.y = f2tf32(kb[i].x);
      w0.z = f2tf32(ka[i].y); w0.w = f2tf32(kb[i].y);
      w1.x = f2tf32(ka[i].z); w1.y = f2tf32(kb[i].z);
      w1.z = f2tf32(ka[i].w); w1.w = f2tf32(kb[i].w);
      ((uint4*)p)[0] = w0;
      ((uint4*)p)[1] = w1;
    }
    // ---- store V frags (scalar scatter, bank-spread) ----
#pragma unroll
    for (int i = 0; i < 2; i++) {
      const int u = tid + i * 256;
      const int g = u >> 3, j2 = u & 7;
      const float vv[8] = {va[i].x, va[i].y, va[i].z, va[i].w,
                           vb[i].x, vb[i].y, vb[i].z, vb[i].w};
      char* base = fsm + VF_OFF + g * 256 + (j2 & 3) * 8 + (j2 >> 2) * 4;
#pragma unroll
      for (int q = 0; q < 8; q++) {
        *(uint32_t*)(base + ((q ^ (g & 7)) * 32)) = f2tf32(vv[q]);
      }
    }
    __syncthreads();

    // ---- per-warp compute (skip fully-masked tiles) ----
    if (k0 <= wrow0 + 15) {
      // S = Q K^T
      float s[8][4];
#pragma unroll
      for (int nt = 0; nt < 8; nt++)
        s[nt][0] = s[nt][1] = s[nt][2] = s[nt][3] = 0.f;
#pragma unroll
      for (int ks = 0; ks < 8; ks++) {
        uint4 qf = *(const uint4*)(fsm + QF_OFF + (warp * 8 + ks) * 512 + qrl16);
#pragma unroll
        for (int nt = 0; nt < 8; nt++) {
          const int g = nt * 8 + ks;
          uint2 kf = *(const uint2*)(fsm + KF_OFF + g * 256 +
                                     (((lane >> 2) ^ (g & 7)) * 32) +
                                     (lane & 3) * 8);
          MMA_TF32(s[nt], qf, kf);
        }
      }

      // causal mask
      const int r0g = wrow0 + (lane >> 2);
      const int r1g = r0g + 8;
      if (k0 + FTK - 1 > wrow0) {
#pragma unroll
        for (int nt = 0; nt < 8; nt++) {
          const int cg = k0 + nt * 8 + 2 * (lane & 3);
          if (cg     > r0g) s[nt][0] = -1e30f;
          if (cg + 1 > r0g) s[nt][1] = -1e30f;
          if (cg     > r1g) s[nt][2] = -1e30f;
          if (cg + 1 > r1g) s[nt][3] = -1e30f;
        }
      }

      // register softmax (rows r0g / r1g, quad-reduced)
      float mx0 = -1e30f, mx1 = -1e30f;
#pragma unroll
      for (int nt = 0; nt < 8; nt++) {
        mx0 = fmaxf(mx0, fmaxf(s[nt][0], s[nt][1]));
        mx1 = fmaxf(mx1, fmaxf(s[nt][2], s[nt][3]));
      }
      mx0 = fmaxf(mx0, __shfl_xor_sync(0xffffffffu, mx0, 1));
      mx0 = fmaxf(mx0, __shfl_xor_sync(0xffffffffu, mx0, 2));
      mx1 = fmaxf(mx1, __shfl_xor_sync(0xffffffffu, mx1, 1));
      mx1 = fmaxf(mx1, __shfl_xor_sync(0xffffffffu, mx1, 2));
      const float mn0 = fmaxf(m0, mx0);
      const float mn1 = fmaxf(m1, mx1);
      const float al0 = __expf(m0 - mn0);
      const float al1 = __expf(m1 - mn1);
      float sum0 = 0.f, sum1 = 0.f;
#pragma unroll
      for (int nt = 0; nt < 8; nt++) {
        s[nt][0] = __expf(s[nt][0] - mn0); sum0 += s[nt][0];
        s[nt][1] = __expf(s[nt][1] - mn0); sum0 += s[nt][1];
        s[nt][2] = __expf(s[nt][2] - mn1); sum1 += s[nt][2];
        s[nt][3] = __expf(s[nt][3] - mn1); sum1 += s[nt][3];
      }
      sum0 += __shfl_xor_sync(0xffffffffu, sum0, 1);
      sum0 += __shfl_xor_sync(0xffffffffu, sum0, 2);
      sum1 += __shfl_xor_sync(0xffffffffu, sum1, 1);
      sum1 += __shfl_xor_sync(0xffffffffu, sum1, 2);
      m0 = mn0; m1 = mn1;
      l0 = l0 * al0 + sum0;
      l1 = l1 * al1 + sum1;

      // build P A-fragments via quad shuffles (acc cols {2j,2j+1} -> {j,j+4})
      uint4 pf[8];
      const int srcA = (lane & ~3) | ((lane & 3) >> 1);
      const int srcB = srcA + 2;
      const bool hi = lane & 1;
#pragma unroll
      for (int ks = 0; ks < 8; ks++) {
        float v0 = __shfl_sync(0xffffffffu, s[ks][0], srcA);
        float v1 = __shfl_sync(0xffffffffu, s[ks][1], srcA);
        float w0 = __shfl_sync(0xffffffffu, s[ks][0], srcB);
        float w1 = __shfl_sync(0xffffffffu, s[ks][1], srcB);
        float x0 = __shfl_sync(0xffffffffu, s[ks][2], srcA);
        float x1 = __shfl_sync(0xffffffffu, s[ks][3], srcA);
        float y0 = __shfl_sync(0xffffffffu, s[ks][2], srcB);
        float y1 = __shfl_sync(0xffffffffu, s[ks][3], srcB);
        pf[ks].x = f2tf32(hi ? v1 : v0);
        pf[ks].y = f2tf32(hi ? x1 : x0);
        pf[ks].z = f2tf32(hi ? w1 : w0);
        pf[ks].w = f2tf32(hi ? y1 : y0);
      }

      // O = O*alpha + P V
#pragma unroll
      for (int nt = 0; nt < 8; nt++) {
        o[nt][0] *= al0; o[nt][1] *= al0;
        o[nt][2] *= al1; o[nt][3] *= al1;
      }
#pragma unroll
      for (int nd = 0; nd < 8; nd++) {
#pragma unroll
        for (int ks = 0; ks < 8; ks++) {
          const int g = nd * 8 + ks;
          uint2 vf = *(const uint2*)(fsm + VF_OFF + g * 256 +
                                     (((lane >> 2) ^ (g & 7)) * 32) +
                                     (lane & 3) * 8);
          MMA_TF32(o[nd], pf[ks], vf);
        }
      }
    }
  }

  // ---- epilogue: normalize, write out[b, q, h*64 + d] ----
  const float i0 = 1.f / l0;
  const float i1 = 1.f / l1;
  const int r0g = q0 + warp * 16 + (lane >> 2);
#pragma unroll
  for (int nd = 0; nd < 8; nd++) {
    const int gc = h * HSD + nd * 8 + 2 * (lane & 3);
    float2 w0 = make_float2(o[nd][0] * i0, o[nd][1] * i0);
    float2 w1 = make_float2(o[nd][2] * i1, o[nd][3] * i1);
    *(float2*)&out[(size_t)(b * TSZ + r0g) * CSZ + gc] = w0;
    *(float2*)&out[(size_t)(b * TSZ + r0g + 8) * CSZ + gc] = w1;
  }
}

// ---------------------------------------------------------------------------
extern "C" void kernel_launch(void* const* d_in, const int* in_sizes, int n_in,
                              void* d_out, int out_size) {
  const float* x    = (const float*)d_in[0];
  const float* W    = (const float*)d_in[1];
  const float* bias = (const float*)d_in[2];
  float* out = (float*)d_out;

  (void)in_sizes; (void)n_in; (void)out_size;

  cudaFuncSetAttribute(qkv_gemm_mma_kernel,
                       cudaFuncAttributeMaxDynamicSharedMemorySize,
                       GSMEM_TOTAL);
  dim3 g1(NC3 / 128, (BSZ * TSZ) / 128);   // (24, 32)
  qkv_gemm_mma_kernel<<<g1, 256, GSMEM_TOTAL>>>(x, W, bias);

  cudaFuncSetAttribute(flash_attn_mma_kernel,
                       cudaFuncAttributeMaxDynamicSharedMemorySize, FSMEM);
  dim3 g2(TSZ / FTQ, NH, BSZ);             // (16, 16, 2)
  flash_attn_mma_kernel<<<g2, 256, FSMEM>>>(out);
}

// round 6
// speedup vs baseline: 1.8479x; 1.1674x over previous
#include <cuda_runtime.h>
#include <math.h>
#include <stdint.h>

// Problem constants
#define BSZ   2
#define TSZ   2048
#define CSZ   1024
#define NH    16
#define HSD   64
#define NC3   3072   // 3*C

// Scratch: qkv = x @ W + b   [B, T, 3C]
__device__ float g_qkv[(size_t)BSZ * TSZ * NC3];
// Prebuilt K/V fragment tiles: [b][h][kt:32][32KB image] (K 16KB + V 16KB)
__device__ float g_kvfrag[(size_t)BSZ * NH * 32 * 8192];

// ===========================================================================
// helpers
// ===========================================================================
__device__ __forceinline__ uint32_t f2tf32(float f) {
  uint32_t r;
  asm("cvt.rna.tf32.f32 %0, %1;" : "=r"(r) : "f"(f));
  return r;
}
__device__ __forceinline__ int uswz(int lane) {
  int q = lane >> 2;
  return (q << 2) | ((lane + q + (q >> 2)) & 3);
}
__device__ __forceinline__ uint32_t smem_u32(const void* p) {
  uint32_t a;
  asm("{ .reg .u64 t; cvta.to.shared.u64 t, %1; cvt.u32.u64 %0, t; }"
      : "=r"(a) : "l"(p));
  return a;
}
#define MMA_TF32(d, a, b)                                                  \
  asm volatile(                                                            \
      "mma.sync.aligned.m16n8k8.row.col.f32.tf32.tf32.f32 "                \
      "{%0,%1,%2,%3}, {%4,%5,%6,%7}, {%8,%9}, {%0,%1,%2,%3};"              \
      : "+f"((d)[0]), "+f"((d)[1]), "+f"((d)[2]), "+f"((d)[3])             \
      : "r"((a).x), "r"((a).y), "r"((a).z), "r"((a).w),                    \
        "r"((b).x), "r"((b).y))
#define CP_ASYNC16(dst, src)                                               \
  asm volatile("cp.async.cg.shared.global [%0], [%1], 16;"                 \
               :: "r"(dst), "l"(src))
#define CP_COMMIT() asm volatile("cp.async.commit_group;" ::: "memory")
#define CP_WAIT0()  asm volatile("cp.async.wait_group 0;" ::: "memory")

// ===========================================================================
// Kernel 1: QKV projection GEMM via mma.sync tf32 (unchanged — at ceiling).
// ===========================================================================
#define GA_BYTES 16384
#define GB_BASE  32768
#define GB_BYTES 16384
#define GSMEM_TOTAL 65536
#define NCHUNK 32

__global__ __launch_bounds__(256, 2) void qkv_gemm_mma_kernel(
    const float* __restrict__ A,
    const float* __restrict__ W,
    const float* __restrict__ bias) {
  extern __shared__ char smem[];
  const int tid  = threadIdx.x;
  const int lane = tid & 31;
  const int warp = tid >> 5;
  const int wm = warp >> 2;
  const int wn = warp & 3;
  const int m0 = blockIdx.y * 128;
  const int n0 = blockIdx.x * 128;

  const int a_tile = tid >> 5;
  const int a_ks   = (tid >> 3) & 3;
  const int a_q    = tid & 7;
  const int a_perm = (a_q + (a_q >> 2)) & 3;
  const float* aP0 =
      A + (size_t)(m0 + a_tile * 16 + a_q) * CSZ + a_ks * 8;
  const int aG = (a_tile * 4 + a_ks) * 512;

  int b_nh[2], b_kk[2], b_ks[2], b_nt[2];
  const float* bP0[2];
  int bG[2];
#pragma unroll
  for (int i = 0; i < 2; i++) {
    int u = tid + i * 256;
    b_nh[i] = u & 1;
    b_kk[i] = (u >> 1) & 3;
    b_ks[i] = (u >> 3) & 3;
    b_nt[i] = u >> 5;
    bP0[i] = W + (size_t)(b_ks[i] * 8 + b_kk[i]) * NC3 + n0 +
             b_nt[i] * 8 + b_nh[i] * 4;
    bG[i] = (b_nt[i] * 4 + b_ks[i]) * 256;
  }

  const int rl16 = uswz(lane) * 16;
  const int rl8  = uswz(lane) * 8;

  float acc[4][4][4] = {};
  float4 ar[4], br[4];

  {
    ar[0] = *(const float4*)(aP0);
    ar[1] = *(const float4*)(aP0 + 8 * CSZ);
    ar[2] = *(const float4*)(aP0 + 4);
    ar[3] = *(const float4*)(aP0 + 8 * CSZ + 4);
#pragma unroll
    for (int i = 0; i < 2; i++) {
      br[2 * i]     = *(const float4*)(bP0[i]);
      br[2 * i + 1] = *(const float4*)(bP0[i] + 4 * NC3);
    }
    char* ab = smem;
    char* bb = smem + GB_BASE;
    const float* arf = (const float*)ar;
#pragma unroll
    for (int j = 0; j < 4; j++) {
      uint4 v;
      v.x = f2tf32(arf[0 * 4 + j]);
      v.y = f2tf32(arf[1 * 4 + j]);
      v.z = f2tf32(arf[2 * 4 + j]);
      v.w = f2tf32(arf[3 * 4 + j]);
      *(uint4*)(ab + aG + (4 * a_q + ((j + a_perm) & 3)) * 16) = v;
    }
    const float* brf = (const float*)br;
#pragma unroll
    for (int i = 0; i < 2; i++) {
#pragma unroll
      for (int j = 0; j < 4; j++) {
        int q = b_nh[i] * 4 + j;
        int slot = 4 * q + ((b_kk[i] + q + (q >> 2)) & 3);
        uint2 v;
        v.x = f2tf32(brf[(2 * i) * 4 + j]);
        v.y = f2tf32(brf[(2 * i + 1) * 4 + j]);
        *(uint2*)(bb + bG[i] + slot * 8) = v;
      }
    }
  }
  __syncthreads();

  for (int c = 0; c < NCHUNK; c++) {
    const char* ab = smem + (c & 1) * GA_BYTES;
    const char* bb = smem + GB_BASE + (c & 1) * GB_BYTES;

    if (c + 1 < NCHUNK) {
      const int ko = (c + 1) * 32;
      ar[0] = *(const float4*)(aP0 + ko);
      ar[1] = *(const float4*)(aP0 + 8 * CSZ + ko);
      ar[2] = *(const float4*)(aP0 + ko + 4);
      ar[3] = *(const float4*)(aP0 + 8 * CSZ + ko + 4);
#pragma unroll
      for (int i = 0; i < 2; i++) {
        br[2 * i]     = *(const float4*)(bP0[i] + (size_t)ko * NC3);
        br[2 * i + 1] = *(const float4*)(bP0[i] + (size_t)(ko + 4) * NC3);
      }
    }

#pragma unroll
    for (int ks = 0; ks < 4; ks++) {
      uint4 af[4];
      uint2 bf[4];
#pragma unroll
      for (int mi = 0; mi < 4; mi++)
        af[mi] = *(const uint4*)(ab + ((wm * 4 + mi) * 4 + ks) * 512 + rl16);
#pragma unroll
      for (int ni = 0; ni < 4; ni++)
        bf[ni] = *(const uint2*)(bb + ((wn * 4 + ni) * 4 + ks) * 256 + rl8);
#pragma unroll
      for (int mi = 0; mi < 4; mi++)
#pragma unroll
        for (int ni = 0; ni < 4; ni++)
          MMA_TF32(acc[mi][ni], af[mi], bf[ni]);
    }

    if (c + 1 < NCHUNK) {
      char* nab = smem + ((c + 1) & 1) * GA_BYTES;
      char* nbb = smem + GB_BASE + ((c + 1) & 1) * GB_BYTES;
      const float* arf = (const float*)ar;
#pragma unroll
      for (int j = 0; j < 4; j++) {
        uint4 v;
        v.x = f2tf32(arf[0 * 4 + j]);
        v.y = f2tf32(arf[1 * 4 + j]);
        v.z = f2tf32(arf[2 * 4 + j]);
        v.w = f2tf32(arf[3 * 4 + j]);
        *(uint4*)(nab + aG + (4 * a_q + ((j + a_perm) & 3)) * 16) = v;
      }
      const float* brf = (const float*)br;
#pragma unroll
      for (int i = 0; i < 2; i++) {
#pragma unroll
        for (int j = 0; j < 4; j++) {
          int q = b_nh[i] * 4 + j;
          int slot = 4 * q + ((b_kk[i] + q + (q >> 2)) & 3);
          uint2 v;
          v.x = f2tf32(brf[(2 * i) * 4 + j]);
          v.y = f2tf32(brf[(2 * i + 1) * 4 + j]);
          *(uint2*)(nbb + bG[i] + slot * 8) = v;
        }
      }
    }
    __syncthreads();
  }

  const int r_base = m0 + wm * 64 + (lane >> 2);
  const int c_base = n0 + wn * 32 + 2 * (lane & 3);
#pragma unroll
  for (int ni = 0; ni < 4; ni++) {
    const int gc = c_base + ni * 8;
    float2 bv = *(const float2*)&bias[gc];
#pragma unroll
    for (int mi = 0; mi < 4; mi++) {
      const int gr = r_base + mi * 16;
      float2 o0 = make_float2(acc[mi][ni][0] + bv.x, acc[mi][ni][1] + bv.y);
      float2 o1 = make_float2(acc[mi][ni][2] + bv.x, acc[mi][ni][3] + bv.y);
      *(float2*)&g_qkv[(size_t)gr * NC3 + gc] = o0;
      *(float2*)&g_qkv[(size_t)(gr + 8) * NC3 + gc] = o1;
    }
  }
}

// ===========================================================================
// Kernel 1.5: build K/V fragment images once per (b,h,kt).
// Produces the exact 32KB smem image flash consumes (K frags 16KB + V 16KB).
// Grid (32, 16, 2), 256 threads, 32KB static smem.
// ===========================================================================
__global__ __launch_bounds__(256) void kv_frag_prep_kernel() {
  __shared__ char psm[32768];
  const int tid = threadIdx.x;
  const int kt = blockIdx.x;
  const int h  = blockIdx.y;
  const int b  = blockIdx.z;
  const int k0 = kt * 64;
  const float* qkv = g_qkv;

#pragma unroll
  for (int i = 0; i < 2; i++) {
    const int u = tid + i * 256;
    const int g = u >> 3;
    // K unit
    {
      const int q = u & 7;
      const float* kp = qkv +
          (size_t)(b * TSZ + k0 + (u >> 6) * 8 + q) * NC3 + CSZ +
          h * HSD + ((u >> 3) & 7) * 8;
      float4 ka = *(const float4*)(kp);
      float4 kb = *(const float4*)(kp + 4);
      char* p = psm + g * 256 + ((q ^ (g & 7)) * 32);
      uint4 w0, w1;
      w0.x = f2tf32(ka.x); w0.y = f2tf32(kb.x);
      w0.z = f2tf32(ka.y); w0.w = f2tf32(kb.y);
      w1.x = f2tf32(ka.z); w1.y = f2tf32(kb.z);
      w1.z = f2tf32(ka.w); w1.w = f2tf32(kb.w);
      ((uint4*)p)[0] = w0;
      ((uint4*)p)[1] = w1;
    }
    // V unit
    {
      const int j2 = u & 7;
      const float* vp = qkv +
          (size_t)(b * TSZ + k0 + ((u >> 3) & 7) * 8 + j2) * NC3 +
          2 * CSZ + h * HSD + (u >> 6) * 8;
      float4 va = *(const float4*)(vp);
      float4 vb = *(const float4*)(vp + 4);
      const float vv[8] = {va.x, va.y, va.z, va.w, vb.x, vb.y, vb.z, vb.w};
      char* base = psm + 16384 + g * 256 + (j2 & 3) * 8 + (j2 >> 2) * 4;
#pragma unroll
      for (int q = 0; q < 8; q++) {
        *(uint32_t*)(base + ((q ^ (g & 7)) * 32)) = f2tf32(vv[q]);
      }
    }
  }
  __syncthreads();

  // linear copy smem image -> gmem
  float4* dst = (float4*)(g_kvfrag + ((size_t)((b * NH + h) * 32 + kt)) * 8192);
  const float4* src = (const float4*)psm;
#pragma unroll
  for (int i = 0; i < 8; i++) {
    const int c = tid + i * 256;
    dst[c] = src[c];
  }
}

// ===========================================================================
// Kernel 2: flash attention on mma.sync tf32 with prebuilt K/V fragments.
// TQ=128 (8 warps x 16 q-rows), TK=64.  K/V tiles arrive via double-buffered
// cp.async (8 LDGSTS.128/thread/tile), ONE barrier per tile.
// Smem: Qf 32KB @0, buf0 32KB @32K, buf1 32KB @64K = 96KB.
// ===========================================================================
#define FTQ 128
#define FTK 64
#define FBUF0 32768
#define FSMEM (96 * 1024)

__global__ __launch_bounds__(256, 2) void flash_attn_mma_kernel(
    float* __restrict__ out) {
  extern __shared__ char fsm[];
  const uint32_t sb = smem_u32(fsm);
  const int tid  = threadIdx.x;
  const int lane = tid & 31;
  const int warp = tid >> 5;
  const int qt = gridDim.x - 1 - blockIdx.x;   // heavy tiles first
  const int h  = blockIdx.y;
  const int b  = blockIdx.z;
  const int q0 = qt * FTQ;
  const float* qkv = g_qkv;
  const float* tiles = g_kvfrag + ((size_t)((b * NH + h) * 32)) * 8192;

  // ---- build Q fragments once (A-frag layout, scaled by 1/8) ----
#pragma unroll
  for (int i = 0; i < 2; i++) {
    const int u = tid + i * 256;
    const int wt = u >> 6, ks = (u >> 3) & 7, q = u & 7;
    const float* qp =
        qkv + (size_t)(b * TSZ + q0 + wt * 16 + q) * NC3 + h * HSD + ks * 8;
    float4 r0a = *(const float4*)(qp);
    float4 r0b = *(const float4*)(qp + 4);
    float4 r1a = *(const float4*)(qp + (size_t)8 * NC3);
    float4 r1b = *(const float4*)(qp + (size_t)8 * NC3 + 4);
    const float r0[8] = {r0a.x, r0a.y, r0a.z, r0a.w, r0b.x, r0b.y, r0b.z, r0b.w};
    const float r1[8] = {r1a.x, r1a.y, r1a.z, r1a.w, r1b.x, r1b.y, r1b.z, r1b.w};
    const int perm = (q + (q >> 2)) & 3;
    char* gb = fsm + (wt * 8 + ks) * 512;
#pragma unroll
    for (int j = 0; j < 4; j++) {
      uint4 v;
      v.x = f2tf32(r0[j] * 0.125f);
      v.y = f2tf32(r1[j] * 0.125f);
      v.z = f2tf32(r0[j + 4] * 0.125f);
      v.w = f2tf32(r1[j + 4] * 0.125f);
      *(uint4*)(gb + (4 * q + ((j + perm) & 3)) * 16) = v;
    }
  }

  // ---- prologue: async-copy tile 0 ----
#pragma unroll
  for (int i = 0; i < 8; i++) {
    const int c = tid + i * 256;
    CP_ASYNC16(sb + FBUF0 + c * 16, (const char*)tiles + c * 16);
  }
  CP_COMMIT();
  CP_WAIT0();
  __syncthreads();   // Q frags + tile 0 visible

  float m0 = -1e30f, m1 = -1e30f, l0 = 0.f, l1 = 0.f;
  float o[8][4] = {};
  const int wrow0 = q0 + warp * 16;
  const int qrl16 = uswz(lane) * 16;
  const int last_kt = 2 * qt + 1;

  for (int kt = 0; kt <= last_kt; kt++) {
    const int cur = kt & 1;

    // ---- async-copy next tile into the other buffer ----
    if (kt < last_kt) {
      const char* src = (const char*)(tiles + (size_t)(kt + 1) * 8192);
      const uint32_t dst = sb + FBUF0 + (1 - cur) * 32768;
#pragma unroll
      for (int i = 0; i < 8; i++) {
        const int c = tid + i * 256;
        CP_ASYNC16(dst + c * 16, src + c * 16);
      }
      CP_COMMIT();
    }

    // ---- per-warp compute from current buffer ----
    const int k0 = kt * FTK;
    if (k0 <= wrow0 + 15) {
      const char* kf = fsm + FBUF0 + cur * 32768;
      const char* vf = kf + 16384;

      // S = Q K^T
      float s[8][4];
#pragma unroll
      for (int nt = 0; nt < 8; nt++)
        s[nt][0] = s[nt][1] = s[nt][2] = s[nt][3] = 0.f;
#pragma unroll
      for (int ks = 0; ks < 8; ks++) {
        uint4 qf = *(const uint4*)(fsm + (warp * 8 + ks) * 512 + qrl16);
#pragma unroll
        for (int nt = 0; nt < 8; nt++) {
          const int g = nt * 8 + ks;
          uint2 kfr = *(const uint2*)(kf + g * 256 +
                                      (((lane >> 2) ^ (g & 7)) * 32) +
                                      (lane & 3) * 8);
          MMA_TF32(s[nt], qf, kfr);
        }
      }

      // causal mask
      const int r0g = wrow0 + (lane >> 2);
      const int r1g = r0g + 8;
      if (k0 + FTK - 1 > wrow0) {
#pragma unroll
        for (int nt = 0; nt < 8; nt++) {
          const int cg = k0 + nt * 8 + 2 * (lane & 3);
          if (cg     > r0g) s[nt][0] = -1e30f;
          if (cg + 1 > r0g) s[nt][1] = -1e30f;
          if (cg     > r1g) s[nt][2] = -1e30f;
          if (cg + 1 > r1g) s[nt][3] = -1e30f;
        }
      }

      // register softmax (rows r0g/r1g, quad-reduced)
      float mx0 = -1e30f, mx1 = -1e30f;
#pragma unroll
      for (int nt = 0; nt < 8; nt++) {
        mx0 = fmaxf(mx0, fmaxf(s[nt][0], s[nt][1]));
        mx1 = fmaxf(mx1, fmaxf(s[nt][2], s[nt][3]));
      }
      mx0 = fmaxf(mx0, __shfl_xor_sync(0xffffffffu, mx0, 1));
      mx0 = fmaxf(mx0, __shfl_xor_sync(0xffffffffu, mx0, 2));
      mx1 = fmaxf(mx1, __shfl_xor_sync(0xffffffffu, mx1, 1));
      mx1 = fmaxf(mx1, __shfl_xor_sync(0xffffffffu, mx1, 2));
      const float mn0 = fmaxf(m0, mx0);
      const float mn1 = fmaxf(m1, mx1);
      const float al0 = __expf(m0 - mn0);
      const float al1 = __expf(m1 - mn1);
      float sum0 = 0.f, sum1 = 0.f;
#pragma unroll
      for (int nt = 0; nt < 8; nt++) {
        s[nt][0] = __expf(s[nt][0] - mn0); sum0 += s[nt][0];
        s[nt][1] = __expf(s[nt][1] - mn0); sum0 += s[nt][1];
        s[nt][2] = __expf(s[nt][2] - mn1); sum1 += s[nt][2];
        s[nt][3] = __expf(s[nt][3] - mn1); sum1 += s[nt][3];
      }
      sum0 += __shfl_xor_sync(0xffffffffu, sum0, 1);
      sum0 += __shfl_xor_sync(0xffffffffu, sum0, 2);
      sum1 += __shfl_xor_sync(0xffffffffu, sum1, 1);
      sum1 += __shfl_xor_sync(0xffffffffu, sum1, 2);
      m0 = mn0; m1 = mn1;
      l0 = l0 * al0 + sum0;
      l1 = l1 * al1 + sum1;

      // build P A-fragments via quad shuffles
      uint4 pf[8];
      const int srcA = (lane & ~3) | ((lane & 3) >> 1);
      const int srcB = srcA + 2;
      const bool hi = lane & 1;
#pragma unroll
      for (int ks = 0; ks < 8; ks++) {
        float v0 = __shfl_sync(0xffffffffu, s[ks][0], srcA);
        float v1 = __shfl_sync(0xffffffffu, s[ks][1], srcA);
        float w0 = __shfl_sync(0xffffffffu, s[ks][0], srcB);
        float w1 = __shfl_sync(0xffffffffu, s[ks][1], srcB);
        float x0 = __shfl_sync(0xffffffffu, s[ks][2], srcA);
        float x1 = __shfl_sync(0xffffffffu, s[ks][3], srcA);
        float y0 = __shfl_sync(0xffffffffu, s[ks][2], srcB);
        float y1 = __shfl_sync(0xffffffffu, s[ks][3], srcB);
        pf[ks].x = f2tf32(hi ? v1 : v0);
        pf[ks].y = f2tf32(hi ? x1 : x0);
        pf[ks].z = f2tf32(hi ? w1 : w0);
        pf[ks].w = f2tf32(hi ? y1 : y0);
      }

      // O = O*alpha + P V
#pragma unroll
      for (int nt = 0; nt < 8; nt++) {
        o[nt][0] *= al0; o[nt][1] *= al0;
        o[nt][2] *= al1; o[nt][3] *= al1;
      }
#pragma unroll
      for (int nd = 0; nd < 8; nd++) {
#pragma unroll
        for (int ks = 0; ks < 8; ks++) {
          const int g = nd * 8 + ks;
          uint2 vfr = *(const uint2*)(vf + g * 256 +
                                      (((lane >> 2) ^ (g & 7)) * 32) +
                                      (lane & 3) * 8);
          MMA_TF32(o[nd], pf[ks], vfr);
        }
      }
    }

    CP_WAIT0();       // next tile's copy done (overlapped with compute)
    __syncthreads();  // single barrier per tile
  }

  // ---- epilogue: normalize, write out[b, q, h*64 + d] ----
  const float i0 = 1.f / l0;
  const float i1 = 1.f / l1;
  const int r0g = q0 + warp * 16 + (lane >> 2);
#pragma unroll
  for (int nd = 0; nd < 8; nd++) {
    const int gc = h * HSD + nd * 8 + 2 * (lane & 3);
    float2 w0 = make_float2(o[nd][0] * i0, o[nd][1] * i0);
    float2 w1 = make_float2(o[nd][2] * i1, o[nd][3] * i1);
    *(float2*)&out[(size_t)(b * TSZ + r0g) * CSZ + gc] = w0;
    *(float2*)&out[(size_t)(b * TSZ + r0g + 8) * CSZ + gc] = w1;
  }
}

// ---------------------------------------------------------------------------
extern "C" void kernel_launch(void* const* d_in, const int* in_sizes, int n_in,
                              void* d_out, int out_size) {
  const float* x    = (const float*)d_in[0];
  const float* W    = (const float*)d_in[1];
  const float* bias = (const float*)d_in[2];
  float* out = (float*)d_out;

  (void)in_sizes; (void)n_in; (void)out_size;

  cudaFuncSetAttribute(qkv_gemm_mma_kernel,
                       cudaFuncAttributeMaxDynamicSharedMemorySize,
                       GSMEM_TOTAL);
  dim3 g1(NC3 / 128, (BSZ * TSZ) / 128);   // (24, 32)
  qkv_gemm_mma_kernel<<<g1, 256, GSMEM_TOTAL>>>(x, W, bias);

  dim3 gp(32, NH, BSZ);                    // (32, 16, 2)
  kv_frag_prep_kernel<<<gp, 256>>>();

  cudaFuncSetAttribute(flash_attn_mma_kernel,
                       cudaFuncAttributeMaxDynamicSharedMemorySize, FSMEM);
  dim3 g2(TSZ / FTQ, NH, BSZ);             // (16, 16, 2)
  flash_attn_mma_kernel<<<g2, 256, FSMEM>>>(out);
}

// round 7
// speedup vs baseline: 4.3980x; 2.3800x over previous
#include <cuda_runtime.h>
#include <math.h>
#include <stdint.h>

// Problem constants
#define BSZ   2
#define TSZ   2048
#define CSZ   1024
#define NH    16
#define HSD   64
#define NC3   3072   // 3*C

// Scratch: qkv = x @ W + b   [B, T, 3C]
__device__ float g_qkv[(size_t)BSZ * TSZ * NC3];
// Prebuilt K/V fragment tiles: [b][h][kt:32][32KB image] (K 16KB + V 16KB)
__device__ float g_kvfrag[(size_t)BSZ * NH * 32 * 8192];
// Prebuilt GEMM operand fragment images (tf32 bits)
__device__ uint32_t g_afrag[(size_t)32 * 32 * 4096];   // [m_blk][chunk][16KB]
__device__ uint32_t g_bfrag[(size_t)24 * 32 * 4096];   // [n_blk][chunk][16KB]

// ===========================================================================
// helpers
// ===========================================================================
__device__ __forceinline__ uint32_t f2tf32(float f) {
  uint32_t r;
  asm("cvt.rna.tf32.f32 %0, %1;" : "=r"(r) : "f"(f));
  return r;
}
__device__ __forceinline__ int uswz(int lane) {
  int q = lane >> 2;
  return (q << 2) | ((lane + q + (q >> 2)) & 3);
}
__device__ __forceinline__ uint32_t smem_u32(const void* p) {
  uint32_t a;
  asm("{ .reg .u64 t; cvta.to.shared.u64 t, %1; cvt.u32.u64 %0, t; }"
      : "=r"(a) : "l"(p));
  return a;
}
#define MMA_TF32(d, a, b)                                                  \
  asm volatile(                                                            \
      "mma.sync.aligned.m16n8k8.row.col.f32.tf32.tf32.f32 "                \
      "{%0,%1,%2,%3}, {%4,%5,%6,%7}, {%8,%9}, {%0,%1,%2,%3};"              \
      : "+f"((d)[0]), "+f"((d)[1]), "+f"((d)[2]), "+f"((d)[3])             \
      : "r"((a).x), "r"((a).y), "r"((a).z), "r"((a).w),                    \
        "r"((b).x), "r"((b).y))
#define CP_ASYNC16(dst, src)                                               \
  asm volatile("cp.async.cg.shared.global [%0], [%1], 16;"                 \
               :: "r"(dst), "l"(src))
#define CP_COMMIT() asm volatile("cp.async.commit_group;" ::: "memory")
#define CP_WAIT0()  asm volatile("cp.async.wait_group 0;" ::: "memory")
#define CP_WAIT1()  asm volatile("cp.async.wait_group 1;" ::: "memory")

// ===========================================================================
// Kernel 0: build GEMM operand fragment images from x and W (runs first).
// grid (32 chunks, 56): y<32 -> A frags for m_blk=y;  y>=32 -> B frags.
// ===========================================================================
__global__ __launch_bounds__(256) void gemm_frag_prep_kernel(
    const float* __restrict__ A,
    const float* __restrict__ W) {
  const int tid = threadIdx.x;
  const int c = blockIdx.x;            // k-chunk 0..31
  if (blockIdx.y < 32) {
    const int m0 = blockIdx.y * 128;
    const int k0 = c * 32;
    const int a_tile = tid >> 5;
    const int a_ks   = (tid >> 3) & 3;
    const int a_q    = tid & 7;
    const int perm = (a_q + (a_q >> 2)) & 3;
    const float* ap =
        A + (size_t)(m0 + a_tile * 16 + a_q) * CSZ + k0 + a_ks * 8;
    float4 r0a = *(const float4*)(ap);
    float4 r0b = *(const float4*)(ap + 4);
    float4 r1a = *(const float4*)(ap + 8 * CSZ);
    float4 r1b = *(const float4*)(ap + 8 * CSZ + 4);
    const float r0[8] = {r0a.x, r0a.y, r0a.z, r0a.w, r0b.x, r0b.y, r0b.z, r0b.w};
    const float r1[8] = {r1a.x, r1a.y, r1a.z, r1a.w, r1b.x, r1b.y, r1b.z, r1b.w};
    char* dst = (char*)g_afrag + ((size_t)(blockIdx.y * 32 + c)) * 16384 +
                (a_tile * 4 + a_ks) * 512;
#pragma unroll
    for (int j = 0; j < 4; j++) {
      uint4 v;
      v.x = f2tf32(r0[j]);
      v.y = f2tf32(r1[j]);
      v.z = f2tf32(r0[j + 4]);
      v.w = f2tf32(r1[j + 4]);
      *(uint4*)(dst + (4 * a_q + ((j + perm) & 3)) * 16) = v;
    }
  } else {
    const int n_blk = blockIdx.y - 32;
    const int n0 = n_blk * 128;
    const int k0 = c * 32;
#pragma unroll
    for (int i = 0; i < 2; i++) {
      const int u = tid + i * 256;
      const int nh = u & 1;
      const int kk = (u >> 1) & 3;
      const int ks = (u >> 3) & 3;
      const int nt = u >> 5;
      const float* bp = W + (size_t)(k0 + ks * 8 + kk) * NC3 + n0 +
                        nt * 8 + nh * 4;
      float4 b0 = *(const float4*)(bp);
      float4 b1 = *(const float4*)(bp + 4 * NC3);
      const float f0[4] = {b0.x, b0.y, b0.z, b0.w};
      const float f1[4] = {b1.x, b1.y, b1.z, b1.w};
      char* dst = (char*)g_bfrag + ((size_t)(n_blk * 32 + c)) * 16384 +
                  (nt * 4 + ks) * 256;
#pragma unroll
      for (int j = 0; j < 4; j++) {
        const int q = nh * 4 + j;
        const int slot = 4 * q + ((kk + q + (q >> 2)) & 3);
        uint2 v;
        v.x = f2tf32(f0[j]);
        v.y = f2tf32(f1[j]);
        *(uint2*)(dst + slot * 8) = v;
      }
    }
  }
}

// ===========================================================================
// Kernel 1: QKV GEMM from prebuilt fragments.  CTA 128x128, K-chunk 32,
// triple-buffered cp.async (one barrier/chunk).  Smem 3x32KB = 96KB.
// ===========================================================================
#define GCHUNK 32768
#define GSMEM_TOTAL (3 * GCHUNK)
#define NCHUNK 32

__global__ __launch_bounds__(256, 2) void qkv_gemm_mma_kernel(
    const float* __restrict__ bias) {
  extern __shared__ char smem[];
  const uint32_t sb = smem_u32(smem);
  const int tid  = threadIdx.x;
  const int lane = tid & 31;
  const int warp = tid >> 5;
  const int wm = warp >> 2;
  const int wn = warp & 3;
  const int m0 = blockIdx.y * 128;
  const int n0 = blockIdx.x * 128;

  const char* asrc0 =
      (const char*)g_afrag + ((size_t)blockIdx.y * 32) * 16384;
  const char* bsrc0 =
      (const char*)g_bfrag + ((size_t)blockIdx.x * 32) * 16384;

  const int rl16 = uswz(lane) * 16;
  const int rl8  = uswz(lane) * 8;

  float acc[4][4][4] = {};

  // prologue: copy chunk 0 into buf 0
#pragma unroll
  for (int i = 0; i < 4; i++) {
    const int off = tid * 16 + i * 4096;
    CP_ASYNC16(sb + off, asrc0 + off);
    CP_ASYNC16(sb + 16384 + off, bsrc0 + off);
  }
  CP_COMMIT();

  for (int c = 0; c < NCHUNK; c++) {
    if (c + 1 < NCHUNK) {
      const uint32_t dst = sb + ((c + 1) % 3) * GCHUNK;
      const char* as = asrc0 + (size_t)(c + 1) * 16384;
      const char* bs = bsrc0 + (size_t)(c + 1) * 16384;
#pragma unroll
      for (int i = 0; i < 4; i++) {
        const int off = tid * 16 + i * 4096;
        CP_ASYNC16(dst + off, as + off);
        CP_ASYNC16(dst + 16384 + off, bs + off);
      }
      CP_COMMIT();
      CP_WAIT1();
    } else {
      CP_WAIT0();
    }
    __syncthreads();

    const char* ab = smem + (c % 3) * GCHUNK;
    const char* bb = ab + 16384;
#pragma unroll
    for (int ks = 0; ks < 4; ks++) {
      uint4 af[4];
      uint2 bf[4];
#pragma unroll
      for (int mi = 0; mi < 4; mi++)
        af[mi] = *(const uint4*)(ab + ((wm * 4 + mi) * 4 + ks) * 512 + rl16);
#pragma unroll
      for (int ni = 0; ni < 4; ni++)
        bf[ni] = *(const uint2*)(bb + ((wn * 4 + ni) * 4 + ks) * 256 + rl8);
#pragma unroll
      for (int mi = 0; mi < 4; mi++)
#pragma unroll
        for (int ni = 0; ni < 4; ni++)
          MMA_TF32(acc[mi][ni], af[mi], bf[ni]);
    }
  }

  // epilogue: acc + bias -> g_qkv
  const int r_base = m0 + wm * 64 + (lane >> 2);
  const int c_base = n0 + wn * 32 + 2 * (lane & 3);
#pragma unroll
  for (int ni = 0; ni < 4; ni++) {
    const int gc = c_base + ni * 8;
    float2 bv = *(const float2*)&bias[gc];
#pragma unroll
    for (int mi = 0; mi < 4; mi++) {
      const int gr = r_base + mi * 16;
      float2 o0 = make_float2(acc[mi][ni][0] + bv.x, acc[mi][ni][1] + bv.y);
      float2 o1 = make_float2(acc[mi][ni][2] + bv.x, acc[mi][ni][3] + bv.y);
      *(float2*)&g_qkv[(size_t)gr * NC3 + gc] = o0;
      *(float2*)&g_qkv[(size_t)(gr + 8) * NC3 + gc] = o1;
    }
  }
}

// ===========================================================================
// Kernel 1.5: build K/V fragment images once per (b,h,kt)  (unchanged).
// ===========================================================================
__global__ __launch_bounds__(256) void kv_frag_prep_kernel() {
  __shared__ char psm[32768];
  const int tid = threadIdx.x;
  const int kt = blockIdx.x;
  const int h  = blockIdx.y;
  const int b  = blockIdx.z;
  const int k0 = kt * 64;
  const float* qkv = g_qkv;

#pragma unroll
  for (int i = 0; i < 2; i++) {
    const int u = tid + i * 256;
    const int g = u >> 3;
    {
      const int q = u & 7;
      const float* kp = qkv +
          (size_t)(b * TSZ + k0 + (u >> 6) * 8 + q) * NC3 + CSZ +
          h * HSD + ((u >> 3) & 7) * 8;
      float4 ka = *(const float4*)(kp);
      float4 kb = *(const float4*)(kp + 4);
      char* p = psm + g * 256 + ((q ^ (g & 7)) * 32);
      uint4 w0, w1;
      w0.x = f2tf32(ka.x); w0.y = f2tf32(kb.x);
      w0.z = f2tf32(ka.y); w0.w = f2tf32(kb.y);
      w1.x = f2tf32(ka.z); w1.y = f2tf32(kb.z);
      w1.z = f2tf32(ka.w); w1.w = f2tf32(kb.w);
      ((uint4*)p)[0] = w0;
      ((uint4*)p)[1] = w1;
    }
    {
      const int j2 = u & 7;
      const float* vp = qkv +
          (size_t)(b * TSZ + k0 + ((u >> 3) & 7) * 8 + j2) * NC3 +
          2 * CSZ + h * HSD + (u >> 6) * 8;
      float4 va = *(const float4*)(vp);
      float4 vb = *(const float4*)(vp + 4);
      const float vv[8] = {va.x, va.y, va.z, va.w, vb.x, vb.y, vb.z, vb.w};
      char* base = psm + 16384 + g * 256 + (j2 & 3) * 8 + (j2 >> 2) * 4;
#pragma unroll
      for (int q = 0; q < 8; q++) {
        *(uint32_t*)(base + ((q ^ (g & 7)) * 32)) = f2tf32(vv[q]);
      }
    }
  }
  __syncthreads();

  float4* dst = (float4*)(g_kvfrag + ((size_t)((b * NH + h) * 32 + kt)) * 8192);
  const float4* src = (const float4*)psm;
#pragma unroll
  for (int i = 0; i < 8; i++) {
    const int c = tid + i * 256;
    dst[c] = src[c];
  }
}

// ===========================================================================
// Kernel 2: flash attention on mma.sync tf32 with prebuilt K/V fragments
// (unchanged from R6).
// ===========================================================================
#define FTQ 128
#define FTK 64
#define FBUF0 32768
#define FSMEM (96 * 1024)

__global__ __launch_bounds__(256, 2) void flash_attn_mma_kernel(
    float* __restrict__ out) {
  extern __shared__ char fsm[];
  const uint32_t sb = smem_u32(fsm);
  const int tid  = threadIdx.x;
  const int lane = tid & 31;
  const int warp = tid >> 5;
  const int qt = gridDim.x - 1 - blockIdx.x;
  const int h  = blockIdx.y;
  const int b  = blockIdx.z;
  const int q0 = qt * FTQ;
  const float* qkv = g_qkv;
  const float* tiles = g_kvfrag + ((size_t)((b * NH + h) * 32)) * 8192;

#pragma unroll
  for (int i = 0; i < 2; i++) {
    const int u = tid + i * 256;
    const int wt = u >> 6, ks = (u >> 3) & 7, q = u & 7;
    const float* qp =
        qkv + (size_t)(b * TSZ + q0 + wt * 16 + q) * NC3 + h * HSD + ks * 8;
    float4 r0a = *(const float4*)(qp);
    float4 r0b = *(const float4*)(qp + 4);
    float4 r1a = *(const float4*)(qp + (size_t)8 * NC3);
    float4 r1b = *(const float4*)(qp + (size_t)8 * NC3 + 4);
    const float r0[8] = {r0a.x, r0a.y, r0a.z, r0a.w, r0b.x, r0b.y, r0b.z, r0b.w};
    const float r1[8] = {r1a.x, r1a.y, r1a.z, r1a.w, r1b.x, r1b.y, r1b.z, r1b.w};
    const int perm = (q + (q >> 2)) & 3;
    char* gb = fsm + (wt * 8 + ks) * 512;
#pragma unroll
    for (int j = 0; j < 4; j++) {
      uint4 v;
      v.x = f2tf32(r0[j] * 0.125f);
      v.y = f2tf32(r1[j] * 0.125f);
      v.z = f2tf32(r0[j + 4] * 0.125f);
      v.w = f2tf32(r1[j + 4] * 0.125f);
      *(uint4*)(gb + (4 * q + ((j + perm) & 3)) * 16) = v;
    }
  }

#pragma unroll
  for (int i = 0; i < 8; i++) {
    const int c = tid + i * 256;
    CP_ASYNC16(sb + FBUF0 + c * 16, (const char*)tiles + c * 16);
  }
  CP_COMMIT();
  CP_WAIT0();
  __syncthreads();

  float m0 = -1e30f, m1 = -1e30f, l0 = 0.f, l1 = 0.f;
  float o[8][4] = {};
  const int wrow0 = q0 + warp * 16;
  const int qrl16 = uswz(lane) * 16;
  const int last_kt = 2 * qt + 1;

  for (int kt = 0; kt <= last_kt; kt++) {
    const int cur = kt & 1;

    if (kt < last_kt) {
      const char* src = (const char*)(tiles + (size_t)(kt + 1) * 8192);
      const uint32_t dst = sb + FBUF0 + (1 - cur) * 32768;
#pragma unroll
      for (int i = 0; i < 8; i++) {
        const int c = tid + i * 256;
        CP_ASYNC16(dst + c * 16, src + c * 16);
      }
      CP_COMMIT();
    }

    const int k0 = kt * FTK;
    if (k0 <= wrow0 + 15) {
      const char* kf = fsm + FBUF0 + cur * 32768;
      const char* vf = kf + 16384;

      float s[8][4];
#pragma unroll
      for (int nt = 0; nt < 8; nt++)
        s[nt][0] = s[nt][1] = s[nt][2] = s[nt][3] = 0.f;
#pragma unroll
      for (int ks = 0; ks < 8; ks++) {
        uint4 qf = *(const uint4*)(fsm + (warp * 8 + ks) * 512 + qrl16);
#pragma unroll
        for (int nt = 0; nt < 8; nt++) {
          const int g = nt * 8 + ks;
          uint2 kfr = *(const uint2*)(kf + g * 256 +
                                      (((lane >> 2) ^ (g & 7)) * 32) +
                                      (lane & 3) * 8);
          MMA_TF32(s[nt], qf, kfr);
        }
      }

      const int r0g = wrow0 + (lane >> 2);
      const int r1g = r0g + 8;
      if (k0 + FTK - 1 > wrow0) {
#pragma unroll
        for (int nt = 0; nt < 8; nt++) {
          const int cg = k0 + nt * 8 + 2 * (lane & 3);
          if (cg     > r0g) s[nt][0] = -1e30f;
          if (cg + 1 > r0g) s[nt][1] = -1e30f;
          if (cg     > r1g) s[nt][2] = -1e30f;
          if (cg + 1 > r1g) s[nt][3] = -1e30f;
        }
      }

      float mx0 = -1e30f, mx1 = -1e30f;
#pragma unroll
      for (int nt = 0; nt < 8; nt++) {
        mx0 = fmaxf(mx0, fmaxf(s[nt][0], s[nt][1]));
        mx1 = fmaxf(mx1, fmaxf(s[nt][2], s[nt][3]));
      }
      mx0 = fmaxf(mx0, __shfl_xor_sync(0xffffffffu, mx0, 1));
      mx0 = fmaxf(mx0, __shfl_xor_sync(0xffffffffu, mx0, 2));
      mx1 = fmaxf(mx1, __shfl_xor_sync(0xffffffffu, mx1, 1));
      mx1 = fmaxf(mx1, __shfl_xor_sync(0xffffffffu, mx1, 2));
      const float mn0 = fmaxf(m0, mx0);
      const float mn1 = fmaxf(m1, mx1);
      const float al0 = __expf(m0 - mn0);
      const float al1 = __expf(m1 - mn1);
      float sum0 = 0.f, sum1 = 0.f;
#pragma unroll
      for (int nt = 0; nt < 8; nt++) {
        s[nt][0] = __expf(s[nt][0] - mn0); sum0 += s[nt][0];
        s[nt][1] = __expf(s[nt][1] - mn0); sum0 += s[nt][1];
        s[nt][2] = __expf(s[nt][2] - mn1); sum1 += s[nt][2];
        s[nt][3] = __expf(s[nt][3] - mn1); sum1 += s[nt][3];
      }
      sum0 += __shfl_xor_sync(0xffffffffu, sum0, 1);
      sum0 += __shfl_xor_sync(0xffffffffu, sum0, 2);
      sum1 += __shfl_xor_sync(0xffffffffu, sum1, 1);
      sum1 += __shfl_xor_sync(0xffffffffu, sum1, 2);
      m0 = mn0; m1 = mn1;
      l0 = l0 * al0 + sum0;
      l1 = l1 * al1 + sum1;

      uint4 pf[8];
      const int srcA = (lane & ~3) | ((lane & 3) >> 1);
      const int srcB = srcA + 2;
      const bool hi = lane & 1;
#pragma unroll
      for (int ks = 0; ks < 8; ks++) {
        float v0 = __shfl_sync(0xffffffffu, s[ks][0], srcA);
        float v1 = __shfl_sync(0xffffffffu, s[ks][1], srcA);
        float w0 = __shfl_sync(0xffffffffu, s[ks][0], srcB);
        float w1 = __shfl_sync(0xffffffffu, s[ks][1], srcB);
        float x0 = __shfl_sync(0xffffffffu, s[ks][2], srcA);
        float x1 = __shfl_sync(0xffffffffu, s[ks][3], srcA);
        float y0 = __shfl_sync(0xffffffffu, s[ks][2], srcB);
        float y1 = __shfl_sync(0xffffffffu, s[ks][3], srcB);
        pf[ks].x = f2tf32(hi ? v1 : v0);
        pf[ks].y = f2tf32(hi ? x1 : x0);
        pf[ks].z = f2tf32(hi ? w1 : w0);
        pf[ks].w = f2tf32(hi ? y1 : y0);
      }

#pragma unroll
      for (int nt = 0; nt < 8; nt++) {
        o[nt][0] *= al0; o[nt][1] *= al0;
        o[nt][2] *= al1; o[nt][3] *= al1;
      }
#pragma unroll
      for (int nd = 0; nd < 8; nd++) {
#pragma unroll
        for (int ks = 0; ks < 8; ks++) {
          const int g = nd * 8 + ks;
          uint2 vfr = *(const uint2*)(vf + g * 256 +
                                      (((lane >> 2) ^ (g & 7)) * 32) +
                                      (lane & 3) * 8);
          MMA_TF32(o[nd], pf[ks], vfr);
        }
      }
    }

    CP_WAIT0();
    __syncthreads();
  }

  const float i0 = 1.f / l0;
  const float i1 = 1.f / l1;
  const int r0g = q0 + warp * 16 + (lane >> 2);
#pragma unroll
  for (int nd = 0; nd < 8; nd++) {
    const int gc = h * HSD + nd * 8 + 2 * (lane & 3);
    float2 w0 = make_float2(o[nd][0] * i0, o[nd][1] * i0);
    float2 w1 = make_float2(o[nd][2] * i1, o[nd][3] * i1);
    *(float2*)&out[(size_t)(b * TSZ + r0g) * CSZ + gc] = w0;
    *(float2*)&out[(size_t)(b * TSZ + r0g + 8) * CSZ + gc] = w1;
  }
}

// ---------------------------------------------------------------------------
extern "C" void kernel_launch(void* const* d_in, const int* in_sizes, int n_in,
                              void* d_out, int out_size) {
  const float* x    = (const float*)d_in[0];
  const float* W    = (const float*)d_in[1];
  const float* bias = (const float*)d_in[2];
  float* out = (float*)d_out;

  (void)in_sizes; (void)n_in; (void)out_size;

  dim3 gp0(32, 56);                        // 32 A-blocks + 24 B-blocks
  gemm_frag_prep_kernel<<<gp0, 256>>>(x, W);

  cudaFuncSetAttribute(qkv_gemm_mma_kernel,
                       cudaFuncAttributeMaxDynamicSharedMemorySize,
                       GSMEM_TOTAL);
  dim3 g1(NC3 / 128, (BSZ * TSZ) / 128);   // (24, 32)
  qkv_gemm_mma_kernel<<<g1, 256, GSMEM_TOTAL>>>(bias);

  dim3 gp(32, NH, BSZ);                    // (32, 16, 2)
  kv_frag_prep_kernel<<<gp, 256>>>();

  cudaFuncSetAttribute(flash_attn_mma_kernel,
                       cudaFuncAttributeMaxDynamicSharedMemorySize, FSMEM);
  dim3 g2(TSZ / FTQ, NH, BSZ);             // (16, 16, 2)
  flash_attn_mma_kernel<<<g2, 256, FSMEM>>>(out);
}